// round 10
// baseline (speedup 1.0000x reference)
#include <cuda_runtime.h>
#include <cuda_bf16.h>

#define SQ 2048
#define DM 1024
#define NH 16
#define DKH 64
#define NHID 1024

typedef unsigned int u32;
typedef unsigned short u16;

// ---------------- scratch ----------------
__device__ char  g_xq0[3*SQ*DM];     // int8 digit0 of activations
__device__ char  g_xq1[3*SQ*DM];     // int8 digit1
__device__ float g_sxa[3*SQ];        // per-row scales
__device__ char  g_wq0[3*NH*DKH*DM]; // weight digits, transposed [(z*64+n)][d]
__device__ char  g_wq1[3*NH*DKH*DM];
__device__ float g_swq[3*NH*DKH];    // per-out-col scales
__device__ u16 g_woth[NHID*DM];      // Wo split transposed [n][k] (bf16 path)
__device__ u16 g_wotl[NHID*DM];
__device__ u16 g_qh[NH*SQ*DKH];
__device__ u16 g_ql[NH*SQ*DKH];
__device__ u16 g_kh[NH*SQ*DKH];
__device__ u16 g_kl[NH*SQ*DKH];
__device__ u16 g_vth[NH*DKH*SQ];     // [h][d][s]
__device__ u16 g_vtl[NH*DKH*SQ];
__device__ u16 g_ch[SQ*NHID];
__device__ u16 g_cl[SQ*NHID];

// ---------------- helpers ----------------
__device__ __forceinline__ void split1(float x, u16& h, u16& l) {
    __nv_bfloat16 hb = __float2bfloat16(x);
    h = __bfloat16_as_ushort(hb);
    l = __bfloat16_as_ushort(__float2bfloat16(x - __bfloat162float(hb)));
}
__device__ __forceinline__ void split_pack(float x0, float x1, u32& h, u32& l) {
    u16 h0,l0,h1,l1;
    split1(x0,h0,l0); split1(x1,h1,l1);
    h = ((u32)h1<<16)|h0; l = ((u32)l1<<16)|l0;
}
__device__ __forceinline__ void mma_bf16(float* c, const u32* a, const u32* b) {
    asm volatile(
      "mma.sync.aligned.m16n8k16.row.col.f32.bf16.bf16.f32 "
      "{%0,%1,%2,%3}, {%4,%5,%6,%7}, {%8,%9}, {%0,%1,%2,%3};\n"
      : "+f"(c[0]), "+f"(c[1]), "+f"(c[2]), "+f"(c[3])
      : "r"(a[0]), "r"(a[1]), "r"(a[2]), "r"(a[3]), "r"(b[0]), "r"(b[1]));
}
__device__ __forceinline__ void mma3(float* c, const u32* ah, const u32* al,
                                     const u32* bh, const u32* bl) {
    mma_bf16(c, ah, bh);
    mma_bf16(c, ah, bl);
    mma_bf16(c, al, bh);
}
__device__ __forceinline__ void imma(int* c, const u32* a, const u32* b) {
    asm volatile(
      "mma.sync.aligned.m16n8k32.row.col.s32.s8.s8.s32 "
      "{%0,%1,%2,%3}, {%4,%5,%6,%7}, {%8,%9}, {%0,%1,%2,%3};\n"
      : "+r"(c[0]), "+r"(c[1]), "+r"(c[2]), "+r"(c[3])
      : "r"(a[0]), "r"(a[1]), "r"(a[2]), "r"(a[3]), "r"(b[0]), "r"(b[1]));
}
__device__ __forceinline__ void cp16(u32 dst_smem, const void* src) {
    asm volatile("cp.async.cg.shared.global [%0], [%1], 16;\n"
                 :: "r"(dst_smem), "l"(src));
}
__device__ __forceinline__ void cp_commit() {
    asm volatile("cp.async.commit_group;\n");
}
template<int N> __device__ __forceinline__ void cp_wait() {
    asm volatile("cp.async.wait_group %0;\n" :: "n"(N));
}
__device__ __forceinline__ void ldsm4(u32& r0, u32& r1, u32& r2, u32& r3, u32 saddr) {
    asm volatile("ldmatrix.sync.aligned.m8n8.x4.shared.b16 {%0,%1,%2,%3}, [%4];\n"
                 : "=r"(r0), "=r"(r1), "=r"(r2), "=r"(r3) : "r"(saddr));
}
// swizzle for 64B logical rows packed into 128B blocks (proven in proj5)
__device__ __forceinline__ u32 swz64(int r, int c) {
    return ((u32)(r>>1)<<7) | ((u32)(r&1)<<6) | ((u32)((c + (r>>1)) & 3)<<4);
}

// ---------------------------------------------------------------------------
// Quant pre-pass: per-row 2-digit int8 of activations (Q|K|V).
// ---------------------------------------------------------------------------
__global__ __launch_bounds__(256) void xquant_kernel(
    const float* __restrict__ Q, const float* __restrict__ K,
    const float* __restrict__ V,
    char* __restrict__ q0, char* __restrict__ q1, float* __restrict__ sxa)
{
    int row = blockIdx.x;                // 0..6143
    int which = row >> 11, m = row & 2047;
    const float* in = ((which==0)?Q:(which==1)?K:V) + (size_t)m*DM;
    int t = threadIdx.x;
    float4 v = *(const float4*)(in + t*4);
    float mx = fmaxf(fmaxf(fabsf(v.x),fabsf(v.y)), fmaxf(fabsf(v.z),fabsf(v.w)));
#pragma unroll
    for (int o=16;o>=1;o>>=1) mx = fmaxf(mx, __shfl_xor_sync(0xffffffffu, mx, o));
    __shared__ float wmax[8];
    __shared__ float sbc;
    if ((t&31)==0) wmax[t>>5] = mx;
    __syncthreads();
    if (t==0){
        float m8 = wmax[0];
#pragma unroll
        for (int i=1;i<8;i++) m8 = fmaxf(m8, wmax[i]);
        sbc = fmaxf(m8, 1e-30f) / 127.f;
        sxa[row] = sbc;
    }
    __syncthreads();
    float inv = 1.f / sbc;
    char d0[4], d1[4];
    float xs[4] = {v.x, v.y, v.z, v.w};
#pragma unroll
    for (int i=0;i<4;i++){
        float q = xs[i]*inv;
        float f0 = rintf(q);
        float f1 = rintf((q - f0)*254.f);
        d0[i] = (char)__float2int_rn(f0);
        d1[i] = (char)__float2int_rn(f1);
    }
    size_t ofs = (size_t)row*DM + t*4;
    *(char4*)(q0 + ofs) = make_char4(d0[0],d0[1],d0[2],d0[3]);
    *(char4*)(q1 + ofs) = make_char4(d1[0],d1[1],d1[2],d1[3]);
}

// per-output-col max of QKV weights -> scales
__global__ void wq_colmax_kernel(
    const float* __restrict__ Wq, const float* __restrict__ Wk,
    const float* __restrict__ Wv, float* __restrict__ swq)
{
    int z = blockIdx.x, which = z>>4, h = z&15;
    const float* W = ((which==0)?Wq:(which==1)?Wk:Wv) + (size_t)h*DM*DKH;
    int tx = threadIdx.x & 63, ty = threadIdx.x >> 6;
    float mx = 0.f;
    for (int d = ty; d < DM; d += 4)
        mx = fmaxf(mx, fabsf(W[(size_t)d*DKH + tx]));
    __shared__ float sm4[4][64];
    sm4[ty][tx] = mx;
    __syncthreads();
    if (ty==0){
        float m = fmaxf(fmaxf(sm4[0][tx],sm4[1][tx]), fmaxf(sm4[2][tx],sm4[3][tx]));
        swq[z*64+tx] = fmaxf(m, 1e-30f) / 127.f;
    }
}

// transpose + quantize QKV weights -> [(z*64+n)][d] int8 digits
__global__ void wq_quant_kernel(
    const float* __restrict__ Wq, const float* __restrict__ Wk,
    const float* __restrict__ Wv, const float* __restrict__ swq,
    char* __restrict__ wq0, char* __restrict__ wq1)
{
    __shared__ float t[32][33];
    int z = blockIdx.z, which = z>>4, h = z&15;
    const float* in = ((which==0)?Wq:(which==1)?Wk:Wv) + (size_t)h*DM*DKH;
    int d0 = blockIdx.x*32, k0 = blockIdx.y*32;
    int tx = threadIdx.x, ty = threadIdx.y;
    t[ty][tx] = in[(size_t)(d0+ty)*DKH + k0+tx];
    __syncthreads();
    float v = t[tx][ty];                       // = in[d0+tx][k0+ty]
    float s = swq[z*64 + k0+ty];
    float q = v/s;
    float f0 = rintf(q);
    float f1 = rintf((q - f0)*254.f);
    size_t o = ((size_t)z*DKH + k0+ty)*DM + d0+tx;
    wq0[o] = (char)__float2int_rn(f0);
    wq1[o] = (char)__float2int_rn(f1);
}

// transpose+split Wo -> [n][k] bf16 planes (unchanged)
__global__ void wsplit_wo_kernel(
    const float* __restrict__ Wo, u16* __restrict__ oh, u16* __restrict__ ol)
{
    __shared__ float t[32][33];
    int k0 = blockIdx.x*32, n0 = blockIdx.y*32;
    int tx = threadIdx.x, ty = threadIdx.y;
    t[ty][tx] = Wo[(size_t)(k0+ty)*DM + n0+tx];
    __syncthreads();
    float v = t[tx][ty];
    u16 hh,ll; split1(v,hh,ll);
    size_t o = ((size_t)(n0+ty))*DM + k0+tx;
    oh[o]=hh; ol[o]=ll;
}

// ---------------------------------------------------------------------------
// proj6: INT8 fused QKV projection. Block 128(M) x 64(N=one head), BK=64 s8.
// 3-stage cp.async pipeline, swz64 smem, LDSM frags, dual s32 acc groups.
// C = sa[m]*sw[n]*(G0 + G1/254); epilogue emits bf16 hi/lo planes as before.
// ---------------------------------------------------------------------------
#define I_A0 0
#define I_A1 8192
#define I_B0 16384
#define I_B1 20480
#define ISTG 24576
#define PROJ6_SMEM (3*ISTG)     // 73728 B
#define IKT 16                  // K=1024 / 64

__global__ __launch_bounds__(256,2) void proj6_kernel(
    const char* __restrict__ xq0, const char* __restrict__ xq1,
    const char* __restrict__ wq0, const char* __restrict__ wq1,
    const float* __restrict__ sxa, const float* __restrict__ swq,
    const float* __restrict__ bq, const float* __restrict__ bk,
    const float* __restrict__ bv,
    u16* __restrict__ oqh, u16* __restrict__ oql,
    u16* __restrict__ okh, u16* __restrict__ okl,
    u16* __restrict__ ovh, u16* __restrict__ ovl)
{
    extern __shared__ u32 sm[];
    const u32 smb = (u32)__cvta_generic_to_shared(sm);
    const int tid = threadIdx.x, lane = tid&31, wid = tid>>5;
    const int g = lane>>2, t4 = lane&3;
    const int wm = wid>>1, wn = wid&1;       // warp tile 32m x 32n
    const int which = blockIdx.z, head = blockIdx.x, m0 = blockIdx.y*128;
    const int z = which*NH + head;

    const char* aq0 = xq0 + (size_t)which*SQ*DM;
    const char* aq1 = xq1 + (size_t)which*SQ*DM;
    const char* bq0 = wq0 + (size_t)z*DKH*DM;
    const char* bq1 = wq1 + (size_t)z*DKH*DM;

    int g0[2][4][4], g1[2][4][4];
#pragma unroll
    for (int i=0;i<2;i++)
#pragma unroll
      for (int j=0;j<4;j++)
#pragma unroll
        for (int e=0;e<4;e++){ g0[i][j][e]=0; g1[i][j][e]=0; }

    auto issue = [&](int kt){
        if (kt < IKT){
            u32 base = (kt%3)*ISTG;
#pragma unroll
            for (int j=0;j<6;j++){
                int i = tid + j*256;              // 0..1535
                const char* src; u32 reg; int idx;
                if (i < 512)       { idx = i;      reg = I_A0; src = aq0 + (size_t)(m0+(idx>>2))*DM + kt*64 + (idx&3)*16; }
                else if (i < 1024) { idx = i-512;  reg = I_A1; src = aq1 + (size_t)(m0+(idx>>2))*DM + kt*64 + (idx&3)*16; }
                else if (i < 1280) { idx = i-1024; reg = I_B0; src = bq0 + (size_t)(idx>>2)*DM + kt*64 + (idx&3)*16; }
                else               { idx = i-1280; reg = I_B1; src = bq1 + (size_t)(idx>>2)*DM + kt*64 + (idx&3)*16; }
                cp16(smb + base + reg + swz64(idx>>2, idx&3), src);
            }
        }
        cp_commit();
    };

    issue(0); issue(1);
    for (int kt=0; kt<IKT; kt++){
        cp_wait<1>();
        __syncthreads();
        issue(kt+2);

        u32 base = smb + (kt%3)*ISTG;
#pragma unroll
        for (int ks=0; ks<2; ks++){
            // B frags: digits 0/1, 4 n-tiles (2 per ldsm4)
            u32 bd0[4][2], bd1[4][2];
#pragma unroll
            for (int half=0; half<2; half++){
                int nrow = wn*32 + half*16 + ((lane>>4)<<3) + (lane&7);
                int cB = ks*2 + ((lane>>3)&1);
                u32 r0,r1,r2,r3;
                ldsm4(r0,r1,r2,r3, base + I_B0 + swz64(nrow, cB));
                bd0[2*half][0]=r0; bd0[2*half][1]=r1; bd0[2*half+1][0]=r2; bd0[2*half+1][1]=r3;
                ldsm4(r0,r1,r2,r3, base + I_B1 + swz64(nrow, cB));
                bd1[2*half][0]=r0; bd1[2*half][1]=r1; bd1[2*half+1][0]=r2; bd1[2*half+1][1]=r3;
            }
#pragma unroll
            for (int mt=0; mt<2; mt++){
                int mrow = wm*32 + mt*16 + ((lane>>3)&1)*8 + (lane&7);
                int cA = ks*2 + (lane>>4);
                u32 ad0[4], ad1[4];
                ldsm4(ad0[0],ad0[1],ad0[2],ad0[3], base + I_A0 + swz64(mrow, cA));
                ldsm4(ad1[0],ad1[1],ad1[2],ad1[3], base + I_A1 + swz64(mrow, cA));
#pragma unroll
                for (int nt=0; nt<4; nt++){
                    imma(g0[mt][nt], ad0, bd0[nt]);
                    imma(g1[mt][nt], ad0, bd1[nt]);
                    imma(g1[mt][nt], ad1, bd0[nt]);
                }
            }
        }
    }

    // epilogue: dequant + bias (+0.125 for Q), split to bf16 planes
    const float* bias = (which==0)?bq:(which==1)?bk:bv;
    const int transposed = (which==2);
    const float osc = (which==0)?0.125f:1.f;
    const float w1 = 1.f/254.f;
#pragma unroll
    for (int mt=0; mt<2; mt++){
        int r0 = m0 + wm*32 + mt*16 + g;
        int r1 = r0 + 8;
        float sa0 = sxa[which*SQ + r0];
        float sa1 = sxa[which*SQ + r1];
#pragma unroll
        for (int nt=0; nt<4; nt++){
            int dc = wn*32 + nt*8 + t4*2;
            float sw0 = swq[z*64 + dc];
            float sw1 = swq[z*64 + dc + 1];
            float b0f = bias[head*DKH + dc];
            float b1f = bias[head*DKH + dc + 1];
            float y0 = sa0*sw0*((float)g0[mt][nt][0] + (float)g1[mt][nt][0]*w1);
            float y1 = sa0*sw1*((float)g0[mt][nt][1] + (float)g1[mt][nt][1]*w1);
            float y2 = sa1*sw0*((float)g0[mt][nt][2] + (float)g1[mt][nt][2]*w1);
            float y3 = sa1*sw1*((float)g0[mt][nt][3] + (float)g1[mt][nt][3]*w1);
            float v0 = (y0 + b0f)*osc, v1 = (y1 + b1f)*osc;
            float v2 = (y2 + b0f)*osc, v3 = (y3 + b1f)*osc;
            if (!transposed){
                u16* outH = (which==0)?oqh:okh;
                u16* outL = (which==0)?oql:okl;
                u32 h,l;
                split_pack(v0,v1,h,l);
                ((u32*)outH)[(head*SQ + r0)*32 + (dc>>1)] = h;
                ((u32*)outL)[(head*SQ + r0)*32 + (dc>>1)] = l;
                split_pack(v2,v3,h,l);
                ((u32*)outH)[(head*SQ + r1)*32 + (dc>>1)] = h;
                ((u32*)outL)[(head*SQ + r1)*32 + (dc>>1)] = l;
            } else {
                u16 h,l;
                split1(v0,h,l); ovh[(head*DKH+dc  )*SQ + r0]=h; ovl[(head*DKH+dc  )*SQ + r0]=l;
                split1(v1,h,l); ovh[(head*DKH+dc+1)*SQ + r0]=h; ovl[(head*DKH+dc+1)*SQ + r0]=l;
                split1(v2,h,l); ovh[(head*DKH+dc  )*SQ + r1]=h; ovl[(head*DKH+dc  )*SQ + r1]=l;
                split1(v3,h,l); ovh[(head*DKH+dc+1)*SQ + r1]=h; ovl[(head*DKH+dc+1)*SQ + r1]=l;
            }
        }
    }
}

// ---------------------------------------------------------------------------
// out5: bf16-split output projection (proven round-9 version, unchanged)
// ---------------------------------------------------------------------------
#define P5_TILE 8192
#define P5_STG  (4*P5_TILE)
#define GEMM5_SMEM (3*P5_STG)
#define NKT 32

__global__ __launch_bounds__(256,2) void out5_kernel(
    const u32* __restrict__ Ah, const u32* __restrict__ Al,
    const u32* __restrict__ Bh, const u32* __restrict__ Bl,
    const float* __restrict__ bias, float* __restrict__ C)
{
    extern __shared__ u32 sm[];
    const u32 smb = (u32)__cvta_generic_to_shared(sm);
    const int tid = threadIdx.x, lane = tid&31, wid = tid>>5;
    const int g = lane>>2, t4 = lane&3;
    const int wm = wid>>2, wn = wid&3;
    const int n0 = blockIdx.x*128, m0 = blockIdx.y*128;

    float acc[4][4][4];
#pragma unroll
    for (int i=0;i<4;i++)
#pragma unroll
      for (int j=0;j<4;j++)
#pragma unroll
        for (int e=0;e<4;e++) acc[i][j][e]=0.f;

    auto issue = [&](int kt){
        if (kt < NKT){
            u32 base = (kt%3)*P5_STG;
#pragma unroll
            for (int j=0;j<8;j++){
                int i = tid + j*256;
                int tile = i>>9, rem = i&511;
                int r = rem>>2, c = rem&3;
                const u32* src;
                if      (tile==0) src = Ah + (size_t)(m0+r)*512 + kt*16 + c*4;
                else if (tile==1) src = Al + (size_t)(m0+r)*512 + kt*16 + c*4;
                else if (tile==2) src = Bh + (size_t)(n0+r)*512 + kt*16 + c*4;
                else              src = Bl + (size_t)(n0+r)*512 + kt*16 + c*4;
                cp16(smb + base + tile*P5_TILE + swz64(r,c), src);
            }
        }
        cp_commit();
    };

    issue(0); issue(1);
    for (int kt=0; kt<NKT; kt++){
        cp_wait<1>();
        __syncthreads();
        issue(kt+2);

        u32 base = smb + (kt%3)*P5_STG;
#pragma unroll
        for (int ks=0; ks<2; ks++){
            u32 bh[2][4], bl[2][4];
#pragma unroll
            for (int p=0;p<2;p++){
                int nb = wn*32 + p*16 + ((lane>>4)<<3) + (lane&7);
                int cB = ks*2 + ((lane>>3)&1);
                u32 w = base + 2*P5_TILE + swz64(nb, cB);
                ldsm4(bh[p][0],bh[p][1],bh[p][2],bh[p][3], w);
                ldsm4(bl[p][0],bl[p][1],bl[p][2],bl[p][3], w + P5_TILE);
            }
#pragma unroll
            for (int i=0;i<4;i++){
                int rowb = wm*64 + i*16 + (lane&15);
                int cA = ks*2 + (lane>>4);
                u32 w = base + swz64(rowb, cA);
                u32 ah[4], al[4];
                ldsm4(ah[0],ah[1],ah[2],ah[3], w);
                ldsm4(al[0],al[1],al[2],al[3], w + P5_TILE);
#pragma unroll
                for (int p=0;p<2;p++){
                    mma3(acc[i][2*p  ], ah, al, bh[p]+0, bl[p]+0);
                    mma3(acc[i][2*p+1], ah, al, bh[p]+2, bl[p]+2);
                }
            }
        }
    }

#pragma unroll
    for (int i=0;i<4;i++){
#pragma unroll
        for (int j=0;j<4;j++){
            int r0 = m0 + wm*64 + i*16 + g;
            int r1 = r0 + 8;
            int col = n0 + wn*32 + j*8 + t4*2;
            C[(size_t)r0*DM + col    ] = acc[i][j][0] + bias[col];
            C[(size_t)r0*DM + col + 1] = acc[i][j][1] + bias[col+1];
            C[(size_t)r1*DM + col    ] = acc[i][j][2] + bias[col];
            C[(size_t)r1*DM + col + 1] = acc[i][j][3] + bias[col+1];
        }
    }
}

// ---------------------------------------------------------------------------
// Flash attention (proven round-6/9 version, unchanged)
// ---------------------------------------------------------------------------
#define AS 36
#define KVW (64*AS)
#define ATTN_WORDS (2*128*AS + 2*4*KVW)
#define ATTN_SMEM (ATTN_WORDS*4)

__global__ __launch_bounds__(256,2) void attn_kernel(
    const u32* __restrict__ Qh, const u32* __restrict__ Ql,
    const u32* __restrict__ Kh, const u32* __restrict__ Kl,
    const u32* __restrict__ Vh, const u32* __restrict__ Vl,
    u16* __restrict__ Ch, u16* __restrict__ Cl)
{
    extern __shared__ u32 sm[];
    const u32 smb = (u32)__cvta_generic_to_shared(sm);

    const int tid = threadIdx.x, lane = tid&31, wid = tid>>5;
    const int g = lane>>2, t4 = lane&3;
    const int h = blockIdx.y, q0 = blockIdx.x*128;
    const int row = wid*16;

#pragma unroll
    for (int j=0;j<8;j++){
        int i = tid + j*256;
        int plane = i>>10, rem = i&1023;
        int r = rem>>3, c = rem&7;
        const u32* src = (plane ? Ql : Qh) + ((size_t)(h*SQ + q0 + r))*32 + c*4;
        cp16(smb + ((plane ? 128*AS : 0) + r*AS + c*4)*4, src);
    }
    cp_commit();

    auto issueKV = [&](int t, int st){
        u32 base = 2*128*AS + st*4*KVW;
#pragma unroll
        for (int j=0;j<2;j++){
            int i = tid + j*256;
            int r = i>>3, c = i&7;
            cp16(smb + (base +           r*AS + c*4)*4, Kh + ((size_t)(h*SQ + t*64 + r))*32 + c*4);
            cp16(smb + (base +   KVW +   r*AS + c*4)*4, Kl + ((size_t)(h*SQ + t*64 + r))*32 + c*4);
            cp16(smb + (base + 2*KVW +   r*AS + c*4)*4, Vh + ((size_t)(h*DKH + r))*1024 + t*32 + c*4);
            cp16(smb + (base + 3*KVW +   r*AS + c*4)*4, Vl + ((size_t)(h*DKH + r))*1024 + t*32 + c*4);
        }
        cp_commit();
    };
    issueKV(0,0);

    float oacc[8][4];
#pragma unroll
    for (int j=0;j<8;j++)
#pragma unroll
        for (int e=0;e<4;e++) oacc[j][e]=0.f;
    float m0r=-1e30f, m1r=-1e30f, l0r=0.f, l1r=0.f;

    for (int t=0; t<SQ/64; t++){
        const int st = t & 1;
        if (t+1 < SQ/64) { issueKV(t+1, st^1); cp_wait<1>(); }
        else cp_wait<0>();
        __syncthreads();

        u32 kbase = 2*128*AS + st*4*KVW;
        u32 vbase = kbase + 2*KVW;

        float sc[8][4];
#pragma unroll
        for (int j=0;j<8;j++)
#pragma unroll
            for (int e=0;e<4;e++) sc[j][e]=0.f;
#pragma unroll
        for (int ks=0;ks<4;ks++){
            u32 qh[4], ql[4];
            int rowb = row + (lane&15);
            u32 wq = rowb*AS + ks*8 + (lane>>4)*4;
            ldsm4(qh[0],qh[1],qh[2],qh[3], smb + wq*4);
            ldsm4(ql[0],ql[1],ql[2],ql[3], smb + (wq + 128*AS)*4);
#pragma unroll
            for (int p=0;p<4;p++){
                int nb = p*16 + ((lane>>4)<<3) + (lane&7);
                u32 w = kbase + nb*AS + ks*8 + ((lane>>3)&1)*4;
                u32 bh[4], bl[4];
                ldsm4(bh[0],bh[1],bh[2],bh[3], smb + w*4);
                ldsm4(bl[0],bl[1],bl[2],bl[3], smb + (w+KVW)*4);
                mma3(sc[2*p  ], qh, ql, bh+0, bl+0);
                mma3(sc[2*p+1], qh, ql, bh+2, bl+2);
            }
        }

        float tm0=-1e30f, tm1=-1e30f;
#pragma unroll
        for (int j=0;j<8;j++){
            tm0 = fmaxf(tm0, fmaxf(sc[j][0], sc[j][1]));
            tm1 = fmaxf(tm1, fmaxf(sc[j][2], sc[j][3]));
        }
        tm0 = fmaxf(tm0, __shfl_xor_sync(0xffffffffu, tm0, 1));
        tm0 = fmaxf(tm0, __shfl_xor_sync(0xffffffffu, tm0, 2));
        tm1 = fmaxf(tm1, __shfl_xor_sync(0xffffffffu, tm1, 1));
        tm1 = fmaxf(tm1, __shfl_xor_sync(0xffffffffu, tm1, 2));
        float mn0 = fmaxf(m0r, tm0), mn1 = fmaxf(m1r, tm1);
        float c0 = __expf(m0r - mn0), c1 = __expf(m1r - mn1);
        float rs0=0.f, rs1=0.f;
#pragma unroll
        for (int j=0;j<8;j++){
            sc[j][0]=__expf(sc[j][0]-mn0); sc[j][1]=__expf(sc[j][1]-mn0);
            sc[j][2]=__expf(sc[j][2]-mn1); sc[j][3]=__expf(sc[j][3]-mn1);
            rs0 += sc[j][0]+sc[j][1]; rs1 += sc[j][2]+sc[j][3];
        }
        rs0 += __shfl_xor_sync(0xffffffffu, rs0, 1);
        rs0 += __shfl_xor_sync(0xffffffffu, rs0, 2);
        rs1 += __shfl_xor_sync(0xffffffffu, rs1, 1);
        rs1 += __shfl_xor_sync(0xffffffffu, rs1, 2);
        l0r = l0r*c0 + rs0; l1r = l1r*c1 + rs1;
        m0r = mn0; m1r = mn1;
#pragma unroll
        for (int j=0;j<8;j++){
            oacc[j][0]*=c0; oacc[j][1]*=c0; oacc[j][2]*=c1; oacc[j][3]*=c1;
        }

#pragma unroll
        for (int s=0;s<4;s++){
            u32 ph[4], pl[4];
            split_pack(sc[2*s  ][0], sc[2*s  ][1], ph[0], pl[0]);
            split_pack(sc[2*s  ][2], sc[2*s  ][3], ph[1], pl[1]);
            split_pack(sc[2*s+1][0], sc[2*s+1][1], ph[2], pl[2]);
            split_pack(sc[2*s+1][2], sc[2*s+1][3], ph[3], pl[3]);
#pragma unroll
            for (int p=0;p<4;p++){
                int nb = p*16 + ((lane>>4)<<3) + (lane&7);
                u32 w = vbase + nb*AS + s*8 + ((lane>>3)&1)*4;
                u32 bh[4], bl[4];
                ldsm4(bh[0],bh[1],bh[2],bh[3], smb + w*4);
                ldsm4(bl[0],bl[1],bl[2],bl[3], smb + (w+KVW)*4);
                mma3(oacc[2*p  ], ph, pl, bh+0, bl+0);
                mma3(oacc[2*p+1], ph, pl, bh+2, bl+2);
            }
        }
        __syncthreads();
    }

    float inv0 = 1.f/l0r, inv1 = 1.f/l1r;
    int r0 = q0 + row + g, r1 = r0+8;
#pragma unroll
    for (int j=0;j<8;j++){
        int col = h*DKH + j*8 + t4*2;
        u32 hh, ll;
        split_pack(oacc[j][0]*inv0, oacc[j][1]*inv0, hh, ll);
        ((u32*)Ch)[(r0*NHID + col)>>1] = hh;
        ((u32*)Cl)[(r0*NHID + col)>>1] = ll;
        split_pack(oacc[j][2]*inv1, oacc[j][3]*inv1, hh, ll);
        ((u32*)Ch)[(r1*NHID + col)>>1] = hh;
        ((u32*)Cl)[(r1*NHID + col)>>1] = ll;
    }
}

// ---------------------------------------------------------------------------
extern "C" void kernel_launch(void* const* d_in, const int* in_sizes, int n_in,
                              void* d_out, int out_size)
{
    const float* Q  = (const float*)d_in[0];
    const float* K  = (const float*)d_in[1];
    const float* V  = (const float*)d_in[2];
    const float* Wq = (const float*)d_in[3];
    const float* bq = (const float*)d_in[4];
    const float* Wk = (const float*)d_in[5];
    const float* bk = (const float*)d_in[6];
    const float* Wv = (const float*)d_in[7];
    const float* bv = (const float*)d_in[8];
    const float* Wo = (const float*)d_in[9];
    const float* bo = (const float*)d_in[10];
    float* out = (float*)d_out;

    char *xq0,*xq1,*wq0,*wq1;
    float *sxa,*swq;
    u16 *woth,*wotl,*qh,*ql,*kh,*kl,*vth,*vtl,*ch,*cl;
    cudaGetSymbolAddress((void**)&xq0,  g_xq0);
    cudaGetSymbolAddress((void**)&xq1,  g_xq1);
    cudaGetSymbolAddress((void**)&wq0,  g_wq0);
    cudaGetSymbolAddress((void**)&wq1,  g_wq1);
    cudaGetSymbolAddress((void**)&sxa,  g_sxa);
    cudaGetSymbolAddress((void**)&swq,  g_swq);
    cudaGetSymbolAddress((void**)&woth, g_woth);
    cudaGetSymbolAddress((void**)&wotl, g_wotl);
    cudaGetSymbolAddress((void**)&qh,   g_qh);
    cudaGetSymbolAddress((void**)&ql,   g_ql);
    cudaGetSymbolAddress((void**)&kh,   g_kh);
    cudaGetSymbolAddress((void**)&kl,   g_kl);
    cudaGetSymbolAddress((void**)&vth,  g_vth);
    cudaGetSymbolAddress((void**)&vtl,  g_vtl);
    cudaGetSymbolAddress((void**)&ch,   g_ch);
    cudaGetSymbolAddress((void**)&cl,   g_cl);

    cudaFuncSetAttribute(proj6_kernel,
                         cudaFuncAttributeMaxDynamicSharedMemorySize, PROJ6_SMEM);
    cudaFuncSetAttribute(out5_kernel,
                         cudaFuncAttributeMaxDynamicSharedMemorySize, GEMM5_SMEM);
    cudaFuncSetAttribute(attn_kernel,
                         cudaFuncAttributeMaxDynamicSharedMemorySize, ATTN_SMEM);

    // pre-passes
    xquant_kernel<<<3*SQ, 256>>>(Q, K, V, xq0, xq1, sxa);
    wq_colmax_kernel<<<48, 256>>>(Wq, Wk, Wv, swq);
    wq_quant_kernel<<<dim3(32,2,48), dim3(32,32)>>>(Wq, Wk, Wv, swq, wq0, wq1);
    wsplit_wo_kernel<<<dim3(32,32), dim3(32,32)>>>(Wo, woth, wotl);

    // INT8 fused QKV projection
    dim3 pg(NH, SQ/128, 3);       // (16, 16, 3)
    proj6_kernel<<<pg, 256, PROJ6_SMEM>>>(xq0, xq1, wq0, wq1, sxa, swq,
                                          bq, bk, bv,
                                          qh, ql, kh, kl, vth, vtl);

    dim3 ag(SQ/128, NH);          // (16, 16)
    attn_kernel<<<ag, 256, ATTN_SMEM>>>((u32*)qh,(u32*)ql,(u32*)kh,(u32*)kl,
                                        (u32*)vth,(u32*)vtl, ch, cl);

    dim3 og(DM/128, SQ/128);      // (8, 16)
    out5_kernel<<<og, 256, GEMM5_SMEM>>>((u32*)ch,(u32*)cl,(u32*)woth,(u32*)wotl,
                                         bo, out);
}

// round 11
// speedup vs baseline: 1.4474x; 1.4474x over previous
#include <cuda_runtime.h>
#include <cuda_fp16.h>

#define SQ 2048
#define DM 1024
#define NH 16
#define DKH 64
#define NHID 1024

typedef unsigned int u32;
typedef unsigned short u16;

// ---------------- scratch planes (fp16) ----------------
__device__ u16 g_xh[3*SQ*DM];        // activation hi
__device__ u16 g_xl[3*SQ*DM];        // activation lo (residual)
__device__ u16 g_wth[3*NH*DKH*DM];   // QKV weights, transposed [(z*64+n)][d], hi only
__device__ u16 g_woth[NHID*DM];      // Wo transposed [n][k], hi only
__device__ u16 g_qh[NH*SQ*DKH];      // q hi
__device__ u16 g_ql[NH*SQ*DKH];      // q lo
__device__ u16 g_kh[NH*SQ*DKH];      // k hi only
__device__ u16 g_vth[NH*DKH*SQ];     // v transposed [h][d][s], hi only
__device__ u16 g_ch[SQ*NHID];        // concat hi
__device__ u16 g_cl[SQ*NHID];        // concat lo

// ---------------- helpers ----------------
__device__ __forceinline__ u16 h16(float x){ return __half_as_ushort(__float2half(x)); }
__device__ __forceinline__ void split1h(float x, u16& h, u16& l) {
    __half hb = __float2half(x);
    h = __half_as_ushort(hb);
    l = __half_as_ushort(__float2half(x - __half2float(hb)));
}
__device__ __forceinline__ void split_packh(float x0, float x1, u32& h, u32& l) {
    u16 h0,l0,h1,l1;
    split1h(x0,h0,l0); split1h(x1,h1,l1);
    h = ((u32)h1<<16)|h0; l = ((u32)l1<<16)|l0;
}
__device__ __forceinline__ u32 packh2(float x0, float x1) {
    return ((u32)h16(x1)<<16) | h16(x0);
}
__device__ __forceinline__ void mma_f16(float* c, const u32* a, const u32* b) {
    asm volatile(
      "mma.sync.aligned.m16n8k16.row.col.f32.f16.f16.f32 "
      "{%0,%1,%2,%3}, {%4,%5,%6,%7}, {%8,%9}, {%0,%1,%2,%3};\n"
      : "+f"(c[0]), "+f"(c[1]), "+f"(c[2]), "+f"(c[3])
      : "r"(a[0]), "r"(a[1]), "r"(a[2]), "r"(a[3]), "r"(b[0]), "r"(b[1]));
}
// 2-term asymmetric split product: (ah + al) * b
__device__ __forceinline__ void mma2(float* c, const u32* ah, const u32* al,
                                     const u32* b) {
    mma_f16(c, ah, b);
    mma_f16(c, al, b);
}
__device__ __forceinline__ void cp16(u32 dst_smem, const void* src) {
    asm volatile("cp.async.cg.shared.global [%0], [%1], 16;\n"
                 :: "r"(dst_smem), "l"(src));
}
__device__ __forceinline__ void cp_commit() {
    asm volatile("cp.async.commit_group;\n");
}
template<int N> __device__ __forceinline__ void cp_wait() {
    asm volatile("cp.async.wait_group %0;\n" :: "n"(N));
}
__device__ __forceinline__ void ldsm4(u32& r0, u32& r1, u32& r2, u32& r3, u32 saddr) {
    asm volatile("ldmatrix.sync.aligned.m8n8.x4.shared.b16 {%0,%1,%2,%3}, [%4];\n"
                 : "=r"(r0), "=r"(r1), "=r"(r2), "=r"(r3) : "r"(saddr));
}
// swizzle for 64B logical rows packed into 128B blocks (proven)
__device__ __forceinline__ u32 swz64(int r, int c) {
    return ((u32)(r>>1)<<7) | ((u32)(r&1)<<6) | ((u32)((c + (r>>1)) & 3)<<4);
}

// ---------------------------------------------------------------------------
// Pre-pass 1: split activations (Q|K|V) -> fp16 hi/lo planes.
// ---------------------------------------------------------------------------
__global__ __launch_bounds__(256) void asplit_kernel(
    const float* __restrict__ Q, const float* __restrict__ K,
    const float* __restrict__ V, u16* __restrict__ oh, u16* __restrict__ ol)
{
    size_t base = ((size_t)blockIdx.x*256 + threadIdx.x)*8;
    int which = (int)(base >> 21);
    size_t rem = base & 2097151;
    const float* in = (which==0)?Q:(which==1)?K:V;
    float4 f0 = *(const float4*)(in+rem);
    float4 f1 = *(const float4*)(in+rem+4);
    u32 h0,l0,h1,l1,h2,l2,h3,l3;
    split_packh(f0.x,f0.y,h0,l0);
    split_packh(f0.z,f0.w,h1,l1);
    split_packh(f1.x,f1.y,h2,l2);
    split_packh(f1.z,f1.w,h3,l3);
    *(uint4*)(oh + base) = make_uint4(h0,h1,h2,h3);
    *(uint4*)(ol + base) = make_uint4(l0,l1,l2,l3);
}

// ---------------------------------------------------------------------------
// Pre-pass 2: transpose QKV weights -> [(z*64 + n)][d], fp16 hi only.
// ---------------------------------------------------------------------------
__global__ void wsplit_qkv_kernel(
    const float* __restrict__ Wq, const float* __restrict__ Wk,
    const float* __restrict__ Wv, u16* __restrict__ oh)
{
    __shared__ float t[32][33];
    int z = blockIdx.z, which = z>>4, h = z&15;
    const float* in = ((which==0)?Wq:(which==1)?Wk:Wv) + (size_t)h*DM*DKH;
    int d0 = blockIdx.x*32, k0 = blockIdx.y*32;
    int tx = threadIdx.x, ty = threadIdx.y;
    t[ty][tx] = in[(size_t)(d0+ty)*DKH + k0+tx];
    __syncthreads();
    float v = t[tx][ty];
    size_t o = ((size_t)z*DKH + k0+ty)*DM + d0+tx;
    oh[o] = h16(v);
}

// Pre-pass 3: transpose Wo -> [n][k], fp16 hi only
__global__ void wsplit_wo_kernel(
    const float* __restrict__ Wo, u16* __restrict__ oh)
{
    __shared__ float t[32][33];
    int k0 = blockIdx.x*32, n0 = blockIdx.y*32;
    int tx = threadIdx.x, ty = threadIdx.y;
    t[ty][tx] = Wo[(size_t)(k0+ty)*DM + n0+tx];
    __syncthreads();
    float v = t[tx][ty];
    size_t o = ((size_t)(n0+ty))*DM + k0+tx;
    oh[o] = h16(v);
}

// ---------------------------------------------------------------------------
// GEMM geometry: 128(M) x 128(N), BK=32. stage = Ah(8KB)+Al(8KB)+Bh(8KB)=24KB;
// 3 stages = 72KB. One __syncthreads per k-tile; prefetch depth 2.
// ---------------------------------------------------------------------------
#define P7_TILE 8192
#define P7_STG  (3*P7_TILE)      // 24576 B
#define GEMM7_SMEM (3*P7_STG)    // 73728 B
#define NKT 32                   // K=1024 / BK=32

// ---- fused QKV projection ----
__global__ __launch_bounds__(256,2) void proj7_kernel(
    const u32* __restrict__ Xh, const u32* __restrict__ Xl,
    const u32* __restrict__ Wth,
    const float* __restrict__ bq, const float* __restrict__ bk,
    const float* __restrict__ bv,
    u16* __restrict__ oqh, u16* __restrict__ oql,
    u16* __restrict__ okh, u16* __restrict__ ovh)
{
    extern __shared__ u32 sm[];
    const u32 smb = (u32)__cvta_generic_to_shared(sm);
    const int tid = threadIdx.x, lane = tid&31, wid = tid>>5;
    const int g = lane>>2, t4 = lane&3;
    const int wm = wid>>2, wn = wid&3;       // 2x4 warps, warp tile 64x32
    const int which = blockIdx.z, head0 = blockIdx.x*2, m0 = blockIdx.y*128;

    const u32* aH = Xh + (size_t)which*(SQ*DM/2);
    const u32* aL = Xl + (size_t)which*(SQ*DM/2);
    const int zrow = (which*NH + head0)*DKH;

    float acc[4][4][4];
#pragma unroll
    for (int i=0;i<4;i++)
#pragma unroll
      for (int j=0;j<4;j++)
#pragma unroll
        for (int e=0;e<4;e++) acc[i][j][e]=0.f;

    auto issue = [&](int kt){
        if (kt < NKT){
            u32 base = (kt%3)*P7_STG;
#pragma unroll
            for (int j=0;j<6;j++){
                int i = tid + j*256;             // 0..1535
                int tile = i>>9, idx = i&511;
                int r = idx>>2, c = idx&3;
                const u32* src;
                if      (tile==0) src = aH  + (size_t)(m0+r)*512   + kt*16 + c*4;
                else if (tile==1) src = aL  + (size_t)(m0+r)*512   + kt*16 + c*4;
                else              src = Wth + (size_t)(zrow+r)*512 + kt*16 + c*4;
                cp16(smb + base + tile*P7_TILE + swz64(r,c), src);
            }
        }
        cp_commit();
    };

    issue(0); issue(1);
    for (int kt=0; kt<NKT; kt++){
        cp_wait<1>();
        __syncthreads();
        issue(kt+2);

        u32 base = smb + (kt%3)*P7_STG;
#pragma unroll
        for (int ks=0; ks<2; ks++){
            u32 b[2][4];
#pragma unroll
            for (int p=0;p<2;p++){
                int nb = wn*32 + p*16 + ((lane>>4)<<3) + (lane&7);
                int cB = ks*2 + ((lane>>3)&1);
                u32 w = base + 2*P7_TILE + swz64(nb, cB);
                ldsm4(b[p][0],b[p][1],b[p][2],b[p][3], w);
            }
#pragma unroll
            for (int i=0;i<4;i++){
                int rowb = wm*64 + i*16 + (lane&15);
                int cA = ks*2 + (lane>>4);
                u32 w = base + swz64(rowb, cA);
                u32 ah[4], al[4];
                ldsm4(ah[0],ah[1],ah[2],ah[3], w);
                ldsm4(al[0],al[1],al[2],al[3], w + P7_TILE);
#pragma unroll
                for (int p=0;p<2;p++){
                    mma2(acc[i][2*p  ], ah, al, b[p]+0);
                    mma2(acc[i][2*p+1], ah, al, b[p]+2);
                }
            }
        }
    }

    // epilogue
    const float* bias = (which==0)?bq:(which==1)?bk:bv;
    const float osc = (which==0)?0.125f:1.f;
#pragma unroll
    for (int i=0;i<4;i++){
#pragma unroll
        for (int j=0;j<4;j++){
            int r0 = m0 + wm*64 + i*16 + g;
            int r1 = r0 + 8;
            int ncol = wn*32 + j*8 + t4*2;
            int head = head0 + (ncol>>6);
            int dc = ncol & 63;
            float b0f = bias[head*DKH + dc];
            float b1f = bias[head*DKH + dc + 1];
            float v0 = (acc[i][j][0] + b0f) * osc;
            float v1 = (acc[i][j][1] + b1f) * osc;
            float v2 = (acc[i][j][2] + b0f) * osc;
            float v3 = (acc[i][j][3] + b1f) * osc;
            if (which==0){                      // Q: hi+lo planes
                u32 h,l;
                split_packh(v0,v1,h,l);
                ((u32*)oqh)[(head*SQ + r0)*32 + (dc>>1)] = h;
                ((u32*)oql)[(head*SQ + r0)*32 + (dc>>1)] = l;
                split_packh(v2,v3,h,l);
                ((u32*)oqh)[(head*SQ + r1)*32 + (dc>>1)] = h;
                ((u32*)oql)[(head*SQ + r1)*32 + (dc>>1)] = l;
            } else if (which==1){               // K: hi only
                ((u32*)okh)[(head*SQ + r0)*32 + (dc>>1)] = packh2(v0,v1);
                ((u32*)okh)[(head*SQ + r1)*32 + (dc>>1)] = packh2(v2,v3);
            } else {                            // V: transposed, hi only
                ovh[(head*DKH+dc  )*SQ + r0] = h16(v0);
                ovh[(head*DKH+dc+1)*SQ + r0] = h16(v1);
                ovh[(head*DKH+dc  )*SQ + r1] = h16(v2);
                ovh[(head*DKH+dc+1)*SQ + r1] = h16(v3);
            }
        }
    }
}

// ---- output projection: A = concat hi/lo, B = Wo hi ----
__global__ __launch_bounds__(256,2) void out7_kernel(
    const u32* __restrict__ Ah, const u32* __restrict__ Al,
    const u32* __restrict__ Bh,
    const float* __restrict__ bias, float* __restrict__ C)
{
    extern __shared__ u32 sm[];
    const u32 smb = (u32)__cvta_generic_to_shared(sm);
    const int tid = threadIdx.x, lane = tid&31, wid = tid>>5;
    const int g = lane>>2, t4 = lane&3;
    const int wm = wid>>2, wn = wid&3;
    const int n0 = blockIdx.x*128, m0 = blockIdx.y*128;

    float acc[4][4][4];
#pragma unroll
    for (int i=0;i<4;i++)
#pragma unroll
      for (int j=0;j<4;j++)
#pragma unroll
        for (int e=0;e<4;e++) acc[i][j][e]=0.f;

    auto issue = [&](int kt){
        if (kt < NKT){
            u32 base = (kt%3)*P7_STG;
#pragma unroll
            for (int j=0;j<6;j++){
                int i = tid + j*256;
                int tile = i>>9, idx = i&511;
                int r = idx>>2, c = idx&3;
                const u32* src;
                if      (tile==0) src = Ah + (size_t)(m0+r)*512 + kt*16 + c*4;
                else if (tile==1) src = Al + (size_t)(m0+r)*512 + kt*16 + c*4;
                else              src = Bh + (size_t)(n0+r)*512 + kt*16 + c*4;
                cp16(smb + base + tile*P7_TILE + swz64(r,c), src);
            }
        }
        cp_commit();
    };

    issue(0); issue(1);
    for (int kt=0; kt<NKT; kt++){
        cp_wait<1>();
        __syncthreads();
        issue(kt+2);

        u32 base = smb + (kt%3)*P7_STG;
#pragma unroll
        for (int ks=0; ks<2; ks++){
            u32 b[2][4];
#pragma unroll
            for (int p=0;p<2;p++){
                int nb = wn*32 + p*16 + ((lane>>4)<<3) + (lane&7);
                int cB = ks*2 + ((lane>>3)&1);
                u32 w = base + 2*P7_TILE + swz64(nb, cB);
                ldsm4(b[p][0],b[p][1],b[p][2],b[p][3], w);
            }
#pragma unroll
            for (int i=0;i<4;i++){
                int rowb = wm*64 + i*16 + (lane&15);
                int cA = ks*2 + (lane>>4);
                u32 w = base + swz64(rowb, cA);
                u32 ah[4], al[4];
                ldsm4(ah[0],ah[1],ah[2],ah[3], w);
                ldsm4(al[0],al[1],al[2],al[3], w + P7_TILE);
#pragma unroll
                for (int p=0;p<2;p++){
                    mma2(acc[i][2*p  ], ah, al, b[p]+0);
                    mma2(acc[i][2*p+1], ah, al, b[p]+2);
                }
            }
        }
    }

#pragma unroll
    for (int i=0;i<4;i++){
#pragma unroll
        for (int j=0;j<4;j++){
            int r0 = m0 + wm*64 + i*16 + g;
            int r1 = r0 + 8;
            int col = n0 + wn*32 + j*8 + t4*2;
            C[(size_t)r0*DM + col    ] = acc[i][j][0] + bias[col];
            C[(size_t)r0*DM + col + 1] = acc[i][j][1] + bias[col+1];
            C[(size_t)r1*DM + col    ] = acc[i][j][2] + bias[col];
            C[(size_t)r1*DM + col + 1] = acc[i][j][3] + bias[col+1];
        }
    }
}

// ---------------------------------------------------------------------------
// Flash attention: Q hi/lo planes, K/V hi-only. cp.async double buffer, LDSM.
// smem (u32 words): Qh[128*AS] Ql[128*AS], 2 stages x (Kh[64*AS] + Vh[64*AS])
// ---------------------------------------------------------------------------
#define AS 36
#define KVW (64*AS)
#define ATTN_WORDS (2*128*AS + 2*2*KVW)
#define ATTN_SMEM (ATTN_WORDS*4)

__global__ __launch_bounds__(256,2) void attn_kernel(
    const u32* __restrict__ Qh, const u32* __restrict__ Ql,
    const u32* __restrict__ Kh, const u32* __restrict__ Vh,
    u16* __restrict__ Ch, u16* __restrict__ Cl)
{
    extern __shared__ u32 sm[];
    const u32 smb = (u32)__cvta_generic_to_shared(sm);

    const int tid = threadIdx.x, lane = tid&31, wid = tid>>5;
    const int g = lane>>2, t4 = lane&3;
    const int h = blockIdx.y, q0 = blockIdx.x*128;
    const int row = wid*16;

    // stage Q planes
#pragma unroll
    for (int j=0;j<8;j++){
        int i = tid + j*256;
        int plane = i>>10, rem = i&1023;
        int r = rem>>3, c = rem&7;
        const u32* src = (plane ? Ql : Qh) + ((size_t)(h*SQ + q0 + r))*32 + c*4;
        cp16(smb + ((plane ? 128*AS : 0) + r*AS + c*4)*4, src);
    }
    cp_commit();

    auto issueKV = [&](int t, int st){
        u32 base = 2*128*AS + st*2*KVW;
#pragma unroll
        for (int j=0;j<2;j++){
            int i = tid + j*256;
            int r = i>>3, c = i&7;
            cp16(smb + (base +       r*AS + c*4)*4, Kh + ((size_t)(h*SQ + t*64 + r))*32 + c*4);
            cp16(smb + (base + KVW + r*AS + c*4)*4, Vh + ((size_t)(h*DKH + r))*1024 + t*32 + c*4);
        }
        cp_commit();
    };
    issueKV(0,0);

    float oacc[8][4];
#pragma unroll
    for (int j=0;j<8;j++)
#pragma unroll
        for (int e=0;e<4;e++) oacc[j][e]=0.f;
    float m0r=-1e30f, m1r=-1e30f, l0r=0.f, l1r=0.f;

    for (int t=0; t<SQ/64; t++){
        const int st = t & 1;
        if (t+1 < SQ/64) { issueKV(t+1, st^1); cp_wait<1>(); }
        else cp_wait<0>();
        __syncthreads();

        u32 kbase = 2*128*AS + st*2*KVW;
        u32 vbase = kbase + KVW;

        // scores
        float sc[8][4];
#pragma unroll
        for (int j=0;j<8;j++)
#pragma unroll
            for (int e=0;e<4;e++) sc[j][e]=0.f;
#pragma unroll
        for (int ks=0;ks<4;ks++){
            u32 qh[4], ql[4];
            int rowb = row + (lane&15);
            u32 wq = rowb*AS + ks*8 + (lane>>4)*4;
            ldsm4(qh[0],qh[1],qh[2],qh[3], smb + wq*4);
            ldsm4(ql[0],ql[1],ql[2],ql[3], smb + (wq + 128*AS)*4);
#pragma unroll
            for (int p=0;p<4;p++){
                int nb = p*16 + ((lane>>4)<<3) + (lane&7);
                u32 w = kbase + nb*AS + ks*8 + ((lane>>3)&1)*4;
                u32 b[4];
                ldsm4(b[0],b[1],b[2],b[3], smb + w*4);
                mma2(sc[2*p  ], qh, ql, b+0);
                mma2(sc[2*p+1], qh, ql, b+2);
            }
        }

        // online softmax (Q pre-scaled by 0.125)
        float tm0=-1e30f, tm1=-1e30f;
#pragma unroll
        for (int j=0;j<8;j++){
            tm0 = fmaxf(tm0, fmaxf(sc[j][0], sc[j][1]));
            tm1 = fmaxf(tm1, fmaxf(sc[j][2], sc[j][3]));
        }
        tm0 = fmaxf(tm0, __shfl_xor_sync(0xffffffffu, tm0, 1));
        tm0 = fmaxf(tm0, __shfl_xor_sync(0xffffffffu, tm0, 2));
        tm1 = fmaxf(tm1, __shfl_xor_sync(0xffffffffu, tm1, 1));
        tm1 = fmaxf(tm1, __shfl_xor_sync(0xffffffffu, tm1, 2));
        float mn0 = fmaxf(m0r, tm0), mn1 = fmaxf(m1r, tm1);
        float c0 = __expf(m0r - mn0), c1 = __expf(m1r - mn1);
        float rs0=0.f, rs1=0.f;
#pragma unroll
        for (int j=0;j<8;j++){
            sc[j][0]=__expf(sc[j][0]-mn0); sc[j][1]=__expf(sc[j][1]-mn0);
            sc[j][2]=__expf(sc[j][2]-mn1); sc[j][3]=__expf(sc[j][3]-mn1);
            rs0 += sc[j][0]+sc[j][1]; rs1 += sc[j][2]+sc[j][3];
        }
        rs0 += __shfl_xor_sync(0xffffffffu, rs0, 1);
        rs0 += __shfl_xor_sync(0xffffffffu, rs0, 2);
        rs1 += __shfl_xor_sync(0xffffffffu, rs1, 1);
        rs1 += __shfl_xor_sync(0xffffffffu, rs1, 2);
        l0r = l0r*c0 + rs0; l1r = l1r*c1 + rs1;
        m0r = mn0; m1r = mn1;
#pragma unroll
        for (int j=0;j<8;j++){
            oacc[j][0]*=c0; oacc[j][1]*=c0; oacc[j][2]*=c1; oacc[j][3]*=c1;
        }

        // PV: P split hi/lo in registers, V hi-only
#pragma unroll
        for (int s=0;s<4;s++){
            u32 ph[4], pl[4];
            split_packh(sc[2*s  ][0], sc[2*s  ][1], ph[0], pl[0]);
            split_packh(sc[2*s  ][2], sc[2*s  ][3], ph[1], pl[1]);
            split_packh(sc[2*s+1][0], sc[2*s+1][1], ph[2], pl[2]);
            split_packh(sc[2*s+1][2], sc[2*s+1][3], ph[3], pl[3]);
#pragma unroll
            for (int p=0;p<4;p++){
                int nb = p*16 + ((lane>>4)<<3) + (lane&7);
                u32 w = vbase + nb*AS + s*8 + ((lane>>3)&1)*4;
                u32 b[4];
                ldsm4(b[0],b[1],b[2],b[3], smb + w*4);
                mma2(oacc[2*p  ], ph, pl, b+0);
                mma2(oacc[2*p+1], ph, pl, b+2);
            }
        }
        __syncthreads();
    }

    // epilogue -> concat planes (fp16 hi/lo)
    float inv0 = 1.f/l0r, inv1 = 1.f/l1r;
    int r0 = q0 + row + g, r1 = r0+8;
#pragma unroll
    for (int j=0;j<8;j++){
        int col = h*DKH + j*8 + t4*2;
        u32 hh, ll;
        split_packh(oacc[j][0]*inv0, oacc[j][1]*inv0, hh, ll);
        ((u32*)Ch)[(r0*NHID + col)>>1] = hh;
        ((u32*)Cl)[(r0*NHID + col)>>1] = ll;
        split_packh(oacc[j][2]*inv1, oacc[j][3]*inv1, hh, ll);
        ((u32*)Ch)[(r1*NHID + col)>>1] = hh;
        ((u32*)Cl)[(r1*NHID + col)>>1] = ll;
    }
}

// ---------------------------------------------------------------------------
extern "C" void kernel_launch(void* const* d_in, const int* in_sizes, int n_in,
                              void* d_out, int out_size)
{
    const float* Q  = (const float*)d_in[0];
    const float* K  = (const float*)d_in[1];
    const float* V  = (const float*)d_in[2];
    const float* Wq = (const float*)d_in[3];
    const float* bq = (const float*)d_in[4];
    const float* Wk = (const float*)d_in[5];
    const float* bk = (const float*)d_in[6];
    const float* Wv = (const float*)d_in[7];
    const float* bv = (const float*)d_in[8];
    const float* Wo = (const float*)d_in[9];
    const float* bo = (const float*)d_in[10];
    float* out = (float*)d_out;

    u16 *xh,*xl,*wth,*woth,*qh,*ql,*kh,*vth,*ch,*cl;
    cudaGetSymbolAddress((void**)&xh,   g_xh);
    cudaGetSymbolAddress((void**)&xl,   g_xl);
    cudaGetSymbolAddress((void**)&wth,  g_wth);
    cudaGetSymbolAddress((void**)&woth, g_woth);
    cudaGetSymbolAddress((void**)&qh,   g_qh);
    cudaGetSymbolAddress((void**)&ql,   g_ql);
    cudaGetSymbolAddress((void**)&kh,   g_kh);
    cudaGetSymbolAddress((void**)&vth,  g_vth);
    cudaGetSymbolAddress((void**)&ch,   g_ch);
    cudaGetSymbolAddress((void**)&cl,   g_cl);

    cudaFuncSetAttribute(proj7_kernel,
                         cudaFuncAttributeMaxDynamicSharedMemorySize, GEMM7_SMEM);
    cudaFuncSetAttribute(out7_kernel,
                         cudaFuncAttributeMaxDynamicSharedMemorySize, GEMM7_SMEM);
    cudaFuncSetAttribute(attn_kernel,
                         cudaFuncAttributeMaxDynamicSharedMemorySize, ATTN_SMEM);

    // pre-passes
    asplit_kernel<<<3*SQ*DM/(256*8), 256>>>(Q, K, V, xh, xl);
    wsplit_qkv_kernel<<<dim3(32,2,48), dim3(32,32)>>>(Wq, Wk, Wv, wth);
    wsplit_wo_kernel<<<dim3(32,32), dim3(32,32)>>>(Wo, woth);

    // fused QKV projection: 128x128 tiles, 3-stage pipeline, fp16 2-term
    dim3 pg(NH/2, SQ/128, 3);     // (8, 16, 3)
    proj7_kernel<<<pg, 256, GEMM7_SMEM>>>((u32*)xh,(u32*)xl,(u32*)wth,
                                          bq, bk, bv,
                                          qh, ql, kh, vth);

    dim3 ag(SQ/128, NH);          // (16, 16)
    attn_kernel<<<ag, 256, ATTN_SMEM>>>((u32*)qh,(u32*)ql,(u32*)kh,(u32*)vth,
                                        ch, cl);

    dim3 og(DM/128, SQ/128);      // (8, 16)
    out7_kernel<<<og, 256, GEMM7_SMEM>>>((u32*)ch,(u32*)cl,(u32*)woth,
                                         bo, out);
}

// round 13
// speedup vs baseline: 1.5392x; 1.0634x over previous
#include <cuda_runtime.h>
#include <cuda_bf16.h>

#define SQ 2048
#define DM 1024
#define NH 16
#define DKH 64
#define NHID 1024

typedef unsigned int u32;
typedef unsigned short u16;

// ---------------- scratch planes (bf16 hi/lo) ----------------
__device__ u16 g_xh[3*SQ*DM];
__device__ u16 g_xl[3*SQ*DM];
__device__ u16 g_wth[3*NH*DKH*DM];   // [(which*16+h)*64+k][d]
__device__ u16 g_wtl[3*NH*DKH*DM];
__device__ u16 g_woth[NHID*DM];      // [n][k]
__device__ u16 g_wotl[NHID*DM];
__device__ u16 g_qh[NH*SQ*DKH];
__device__ u16 g_ql[NH*SQ*DKH];
__device__ u16 g_kh[NH*SQ*DKH];
__device__ u16 g_kl[NH*SQ*DKH];
__device__ u16 g_vth[NH*DKH*SQ];     // [h][d][s]
__device__ u16 g_vtl[NH*DKH*SQ];
__device__ u16 g_ch[SQ*NHID];
__device__ u16 g_cl[SQ*NHID];

// ---------------- helpers ----------------
__device__ __forceinline__ void split1(float x, u16& h, u16& l) {
    __nv_bfloat16 hb = __float2bfloat16(x);
    h = __bfloat16_as_ushort(hb);
    l = __bfloat16_as_ushort(__float2bfloat16(x - __bfloat162float(hb)));
}
__device__ __forceinline__ void split_pack(float x0, float x1, u32& h, u32& l) {
    u16 h0,l0,h1,l1;
    split1(x0,h0,l0); split1(x1,h1,l1);
    h = ((u32)h1<<16)|h0; l = ((u32)l1<<16)|l0;
}
__device__ __forceinline__ void mma_bf16(float* c, const u32* a, const u32* b) {
    asm volatile(
      "mma.sync.aligned.m16n8k16.row.col.f32.bf16.bf16.f32 "
      "{%0,%1,%2,%3}, {%4,%5,%6,%7}, {%8,%9}, {%0,%1,%2,%3};\n"
      : "+f"(c[0]), "+f"(c[1]), "+f"(c[2]), "+f"(c[3])
      : "r"(a[0]), "r"(a[1]), "r"(a[2]), "r"(a[3]), "r"(b[0]), "r"(b[1]));
}
__device__ __forceinline__ void mma3(float* c, const u32* ah, const u32* al,
                                     const u32* bh, const u32* bl) {
    mma_bf16(c, ah, bh);
    mma_bf16(c, ah, bl);
    mma_bf16(c, al, bh);
}
__device__ __forceinline__ void cp16(u32 dst_smem, const void* src) {
    asm volatile("cp.async.cg.shared.global [%0], [%1], 16;\n"
                 :: "r"(dst_smem), "l"(src));
}
__device__ __forceinline__ void cp_commit() {
    asm volatile("cp.async.commit_group;\n");
}
template<int N> __device__ __forceinline__ void cp_wait() {
    asm volatile("cp.async.wait_group %0;\n" :: "n"(N));
}
__device__ __forceinline__ void ldsm4(u32& r0, u32& r1, u32& r2, u32& r3, u32 saddr) {
    asm volatile("ldmatrix.sync.aligned.m8n8.x4.shared.b16 {%0,%1,%2,%3}, [%4];\n"
                 : "=r"(r0), "=r"(r1), "=r"(r2), "=r"(r3) : "r"(saddr));
}
// swizzled byte offset for 64B logical rows packed into 128B blocks (proven)
__device__ __forceinline__ u32 swz64(int r, int c) {
    return ((u32)(r>>1)<<7) | ((u32)(r&1)<<6) | ((u32)((c + (r>>1)) & 3)<<4);
}

// ---------------------------------------------------------------------------
// Pre-pass kernels (proven round-9 versions)
// ---------------------------------------------------------------------------
__global__ __launch_bounds__(256) void asplit_kernel(
    const float* __restrict__ Q, const float* __restrict__ K,
    const float* __restrict__ V, u16* __restrict__ oh, u16* __restrict__ ol)
{
    size_t base = ((size_t)blockIdx.x*256 + threadIdx.x)*8;
    int which = (int)(base >> 21);
    size_t rem = base & 2097151;
    const float* in = (which==0)?Q:(which==1)?K:V;
    float4 f0 = *(const float4*)(in+rem);
    float4 f1 = *(const float4*)(in+rem+4);
    u32 h0,l0,h1,l1,h2,l2,h3,l3;
    split_pack(f0.x,f0.y,h0,l0);
    split_pack(f0.z,f0.w,h1,l1);
    split_pack(f1.x,f1.y,h2,l2);
    split_pack(f1.z,f1.w,h3,l3);
    *(uint4*)(oh + base) = make_uint4(h0,h1,h2,h3);
    *(uint4*)(ol + base) = make_uint4(l0,l1,l2,l3);
}

__global__ void wsplit_qkv_kernel(
    const float* __restrict__ Wq, const float* __restrict__ Wk,
    const float* __restrict__ Wv, u16* __restrict__ oh, u16* __restrict__ ol)
{
    __shared__ float t[32][33];
    int z = blockIdx.z, which = z>>4, h = z&15;
    const float* in = ((which==0)?Wq:(which==1)?Wk:Wv) + (size_t)h*DM*DKH;
    int d0 = blockIdx.x*32, k0 = blockIdx.y*32;
    int tx = threadIdx.x, ty = threadIdx.y;
    t[ty][tx] = in[(size_t)(d0+ty)*DKH + k0+tx];
    __syncthreads();
    float v = t[tx][ty];
    u16 hh,ll; split1(v,hh,ll);
    size_t o = ((size_t)z*DKH + k0+ty)*DM + d0+tx;
    oh[o]=hh; ol[o]=ll;
}

__global__ void wsplit_wo_kernel(
    const float* __restrict__ Wo, u16* __restrict__ oh, u16* __restrict__ ol)
{
    __shared__ float t[32][33];
    int k0 = blockIdx.x*32, n0 = blockIdx.y*32;
    int tx = threadIdx.x, ty = threadIdx.y;
    t[ty][tx] = Wo[(size_t)(k0+ty)*DM + n0+tx];
    __syncthreads();
    float v = t[tx][ty];
    u16 hh,ll; split1(v,hh,ll);
    size_t o = ((size_t)(n0+ty))*DM + k0+tx;
    oh[o]=hh; ol[o]=ll;
}

// ---------------------------------------------------------------------------
// GEMM geometry: 64(M) x 128(N) tiles, BK=32.
// stage = Ah(4KB)+Al(4KB)+Bh(8KB)+Bl(8KB) = 24KB; 3 stages = 72KB.
// 8 warps as 2(m) x 4(n), warp tile 32x32 (acc = 32 regs) -> 3 CTAs/SM target.
// Grid 768 (proj) / 256 (out): 86.5% wave fill vs 65%/43% before.
// ---------------------------------------------------------------------------
#define A8_TILE 4096
#define B8_TILE 8192
#define STG8 24576
#define GEMM8_SMEM (3*STG8)     // 73728 B
#define NKT 32                  // K=1024 / BK=32

// shared mainloop body via macro-free duplication (proj & out differ only in
// global pointers + epilogue)

// ---- fused QKV projection ----
__global__ __launch_bounds__(256,3) void proj8_kernel(
    const u32* __restrict__ Xh, const u32* __restrict__ Xl,
    const u32* __restrict__ Wth, const u32* __restrict__ Wtl,
    const float* __restrict__ bq, const float* __restrict__ bk,
    const float* __restrict__ bv,
    u16* __restrict__ oqh, u16* __restrict__ oql,
    u16* __restrict__ okh, u16* __restrict__ okl,
    u16* __restrict__ ovh, u16* __restrict__ ovl)
{
    extern __shared__ u32 sm[];
    const u32 smb = (u32)__cvta_generic_to_shared(sm);
    const int tid = threadIdx.x, lane = tid&31, wid = tid>>5;
    const int g = lane>>2, t4 = lane&3;
    const int wm = wid>>2, wn = wid&3;       // 2x4 warps, warp tile 32x32
    const int which = blockIdx.z, head0 = blockIdx.x*2, m0 = blockIdx.y*64;

    const u32* aH = Xh + (size_t)which*(SQ*DM/2);
    const u32* aL = Xl + (size_t)which*(SQ*DM/2);
    const int zrow = (which*NH + head0)*DKH;

    float acc[2][4][4];
#pragma unroll
    for (int i=0;i<2;i++)
#pragma unroll
      for (int j=0;j<4;j++)
#pragma unroll
        for (int e=0;e<4;e++) acc[i][j][e]=0.f;

    auto issue = [&](int kt){
        if (kt < NKT){
            u32 base = (kt%3)*STG8;
#pragma unroll
            for (int j=0;j<6;j++){
                int i = tid + j*256;             // 0..1535 chunks
                const u32* src; u32 reg; int idx;
                if (i < 256)       { idx = i;       reg = 0;          src = aH  + (size_t)(m0+(idx>>2))*512   + kt*16 + (idx&3)*4; }
                else if (i < 512)  { idx = i-256;   reg = A8_TILE;    src = aL  + (size_t)(m0+(idx>>2))*512   + kt*16 + (idx&3)*4; }
                else if (i < 1024) { idx = i-512;   reg = 2*A8_TILE;  src = Wth + (size_t)(zrow+(idx>>2))*512 + kt*16 + (idx&3)*4; }
                else               { idx = i-1024;  reg = 2*A8_TILE+B8_TILE; src = Wtl + (size_t)(zrow+(idx>>2))*512 + kt*16 + (idx&3)*4; }
                cp16(smb + base + reg + swz64(idx>>2, idx&3), src);
            }
        }
        cp_commit();
    };

    issue(0); issue(1);
    for (int kt=0; kt<NKT; kt++){
        cp_wait<1>();
        __syncthreads();
        issue(kt+2);

        u32 base = smb + (kt%3)*STG8;
#pragma unroll
        for (int ks=0; ks<2; ks++){
            u32 bh[2][4], bl[2][4];
#pragma unroll
            for (int p=0;p<2;p++){
                int nb = wn*32 + p*16 + ((lane>>4)<<3) + (lane&7);
                int cB = ks*2 + ((lane>>3)&1);
                u32 w = base + 2*A8_TILE + swz64(nb, cB);
                ldsm4(bh[p][0],bh[p][1],bh[p][2],bh[p][3], w);
                ldsm4(bl[p][0],bl[p][1],bl[p][2],bl[p][3], w + B8_TILE);
            }
#pragma unroll
            for (int mt=0; mt<2; mt++){
                int rowb = wm*32 + mt*16 + (lane&15);
                int cA = ks*2 + (lane>>4);
                u32 w = base + swz64(rowb, cA);
                u32 ah[4], al[4];
                ldsm4(ah[0],ah[1],ah[2],ah[3], w);
                ldsm4(al[0],al[1],al[2],al[3], w + A8_TILE);
#pragma unroll
                for (int p=0;p<2;p++){
                    mma3(acc[mt][2*p  ], ah, al, bh[p]+0, bl[p]+0);
                    mma3(acc[mt][2*p+1], ah, al, bh[p]+2, bl[p]+2);
                }
            }
        }
    }

    // epilogue (identical math to proven round-9)
    const float* bias = (which==0)?bq:(which==1)?bk:bv;
    const int transposed = (which==2);
    const float osc = (which==0)?0.125f:1.f;
#pragma unroll
    for (int mt=0; mt<2; mt++){
#pragma unroll
        for (int nt=0; nt<4; nt++){
            int r0 = m0 + wm*32 + mt*16 + g;
            int r1 = r0 + 8;
            int ncol = wn*32 + nt*8 + t4*2;
            int head = head0 + (ncol>>6);
            int dc = ncol & 63;
            float b0f = bias[head*DKH + dc];
            float b1f = bias[head*DKH + dc + 1];
            float v0 = (acc[mt][nt][0] + b0f) * osc;
            float v1 = (acc[mt][nt][1] + b1f) * osc;
            float v2 = (acc[mt][nt][2] + b0f) * osc;
            float v3 = (acc[mt][nt][3] + b1f) * osc;
            if (!transposed) {
                u16* outH = (which==0)?oqh:okh;
                u16* outL = (which==0)?oql:okl;
                u32 h,l;
                split_pack(v0,v1,h,l);
                ((u32*)outH)[(head*SQ + r0)*32 + (dc>>1)] = h;
                ((u32*)outL)[(head*SQ + r0)*32 + (dc>>1)] = l;
                split_pack(v2,v3,h,l);
                ((u32*)outH)[(head*SQ + r1)*32 + (dc>>1)] = h;
                ((u32*)outL)[(head*SQ + r1)*32 + (dc>>1)] = l;
            } else {
                u16 h,l;
                split1(v0,h,l); ovh[(head*DKH+dc  )*SQ + r0]=h; ovl[(head*DKH+dc  )*SQ + r0]=l;
                split1(v1,h,l); ovh[(head*DKH+dc+1)*SQ + r0]=h; ovl[(head*DKH+dc+1)*SQ + r0]=l;
                split1(v2,h,l); ovh[(head*DKH+dc  )*SQ + r1]=h; ovl[(head*DKH+dc  )*SQ + r1]=l;
                split1(v3,h,l); ovh[(head*DKH+dc+1)*SQ + r1]=h; ovl[(head*DKH+dc+1)*SQ + r1]=l;
            }
        }
    }
}

// ---- output projection: same 64x128 shape ----
__global__ __launch_bounds__(256,3) void out8_kernel(
    const u32* __restrict__ Ah, const u32* __restrict__ Al,
    const u32* __restrict__ Bh, const u32* __restrict__ Bl,
    const float* __restrict__ bias, float* __restrict__ C)
{
    extern __shared__ u32 sm[];
    const u32 smb = (u32)__cvta_generic_to_shared(sm);
    const int tid = threadIdx.x, lane = tid&31, wid = tid>>5;
    const int g = lane>>2, t4 = lane&3;
    const int wm = wid>>2, wn = wid&3;
    const int n0 = blockIdx.x*128, m0 = blockIdx.y*64;

    float acc[2][4][4];
#pragma unroll
    for (int i=0;i<2;i++)
#pragma unroll
      for (int j=0;j<4;j++)
#pragma unroll
        for (int e=0;e<4;e++) acc[i][j][e]=0.f;

    auto issue = [&](int kt){
        if (kt < NKT){
            u32 base = (kt%3)*STG8;
#pragma unroll
            for (int j=0;j<6;j++){
                int i = tid + j*256;
                const u32* src; u32 reg; int idx;
                if (i < 256)       { idx = i;       reg = 0;          src = Ah + (size_t)(m0+(idx>>2))*512 + kt*16 + (idx&3)*4; }
                else if (i < 512)  { idx = i-256;   reg = A8_TILE;    src = Al + (size_t)(m0+(idx>>2))*512 + kt*16 + (idx&3)*4; }
                else if (i < 1024) { idx = i-512;   reg = 2*A8_TILE;  src = Bh + (size_t)(n0+(idx>>2))*512 + kt*16 + (idx&3)*4; }
                else               { idx = i-1024;  reg = 2*A8_TILE+B8_TILE; src = Bl + (size_t)(n0+(idx>>2))*512 + kt*16 + (idx&3)*4; }
                cp16(smb + base + reg + swz64(idx>>2, idx&3), src);
            }
        }
        cp_commit();
    };

    issue(0); issue(1);
    for (int kt=0; kt<NKT; kt++){
        cp_wait<1>();
        __syncthreads();
        issue(kt+2);

        u32 base = smb + (kt%3)*STG8;
#pragma unroll
        for (int ks=0; ks<2; ks++){
            u32 bh[2][4], bl[2][4];
#pragma unroll
            for (int p=0;p<2;p++){
                int nb = wn*32 + p*16 + ((lane>>4)<<3) + (lane&7);
                int cB = ks*2 + ((lane>>3)&1);
                u32 w = base + 2*A8_TILE + swz64(nb, cB);
                ldsm4(bh[p][0],bh[p][1],bh[p][2],bh[p][3], w);
                ldsm4(bl[p][0],bl[p][1],bl[p][2],bl[p][3], w + B8_TILE);
            }
#pragma unroll
            for (int mt=0; mt<2; mt++){
                int rowb = wm*32 + mt*16 + (lane&15);
                int cA = ks*2 + (lane>>4);
                u32 w = base + swz64(rowb, cA);
                u32 ah[4], al[4];
                ldsm4(ah[0],ah[1],ah[2],ah[3], w);
                ldsm4(al[0],al[1],al[2],al[3], w + A8_TILE);
#pragma unroll
                for (int p=0;p<2;p++){
                    mma3(acc[mt][2*p  ], ah, al, bh[p]+0, bl[p]+0);
                    mma3(acc[mt][2*p+1], ah, al, bh[p]+2, bl[p]+2);
                }
            }
        }
    }

#pragma unroll
    for (int mt=0; mt<2; mt++){
#pragma unroll
        for (int nt=0; nt<4; nt++){
            int r0 = m0 + wm*32 + mt*16 + g;
            int r1 = r0 + 8;
            int col = n0 + wn*32 + nt*8 + t4*2;
            C[(size_t)r0*DM + col    ] = acc[mt][nt][0] + bias[col];
            C[(size_t)r0*DM + col + 1] = acc[mt][nt][1] + bias[col+1];
            C[(size_t)r1*DM + col    ] = acc[mt][nt][2] + bias[col];
            C[(size_t)r1*DM + col + 1] = acc[mt][nt][3] + bias[col+1];
        }
    }
}

// ---------------------------------------------------------------------------
// Flash attention (proven round-9 version, unchanged)
// ---------------------------------------------------------------------------
#define AS 36
#define KVW (64*AS)
#define ATTN_WORDS (2*128*AS + 2*4*KVW)
#define ATTN_SMEM (ATTN_WORDS*4)

__global__ __launch_bounds__(256,2) void attn_kernel(
    const u32* __restrict__ Qh, const u32* __restrict__ Ql,
    const u32* __restrict__ Kh, const u32* __restrict__ Kl,
    const u32* __restrict__ Vh, const u32* __restrict__ Vl,
    u16* __restrict__ Ch, u16* __restrict__ Cl)
{
    extern __shared__ u32 sm[];
    const u32 smb = (u32)__cvta_generic_to_shared(sm);

    const int tid = threadIdx.x, lane = tid&31, wid = tid>>5;
    const int g = lane>>2, t4 = lane&3;
    const int h = blockIdx.y, q0 = blockIdx.x*128;
    const int row = wid*16;

#pragma unroll
    for (int j=0;j<8;j++){
        int i = tid + j*256;
        int plane = i>>10, rem = i&1023;
        int r = rem>>3, c = rem&7;
        const u32* src = (plane ? Ql : Qh) + ((size_t)(h*SQ + q0 + r))*32 + c*4;
        cp16(smb + ((plane ? 128*AS : 0) + r*AS + c*4)*4, src);
    }
    cp_commit();

    auto issueKV = [&](int t, int st){
        u32 base = 2*128*AS + st*4*KVW;
#pragma unroll
        for (int j=0;j<2;j++){
            int i = tid + j*256;
            int r = i>>3, c = i&7;
            cp16(smb + (base +           r*AS + c*4)*4, Kh + ((size_t)(h*SQ + t*64 + r))*32 + c*4);
            cp16(smb + (base +   KVW +   r*AS + c*4)*4, Kl + ((size_t)(h*SQ + t*64 + r))*32 + c*4);
            cp16(smb + (base + 2*KVW +   r*AS + c*4)*4, Vh + ((size_t)(h*DKH + r))*1024 + t*32 + c*4);
            cp16(smb + (base + 3*KVW +   r*AS + c*4)*4, Vl + ((size_t)(h*DKH + r))*1024 + t*32 + c*4);
        }
        cp_commit();
    };
    issueKV(0,0);

    float oacc[8][4];
#pragma unroll
    for (int j=0;j<8;j++)
#pragma unroll
        for (int e=0;e<4;e++) oacc[j][e]=0.f;
    float m0r=-1e30f, m1r=-1e30f, l0r=0.f, l1r=0.f;

    for (int t=0; t<SQ/64; t++){
        const int st = t & 1;
        if (t+1 < SQ/64) { issueKV(t+1, st^1); cp_wait<1>(); }
        else cp_wait<0>();
        __syncthreads();

        u32 kbase = 2*128*AS + st*4*KVW;
        u32 vbase = kbase + 2*KVW;

        float sc[8][4];
#pragma unroll
        for (int j=0;j<8;j++)
#pragma unroll
            for (int e=0;e<4;e++) sc[j][e]=0.f;
#pragma unroll
        for (int ks=0;ks<4;ks++){
            u32 qh[4], ql[4];
            int rowb = row + (lane&15);
            u32 wq = rowb*AS + ks*8 + (lane>>4)*4;
            ldsm4(qh[0],qh[1],qh[2],qh[3], smb + wq*4);
            ldsm4(ql[0],ql[1],ql[2],ql[3], smb + (wq + 128*AS)*4);
#pragma unroll
            for (int p=0;p<4;p++){
                int nb = p*16 + ((lane>>4)<<3) + (lane&7);
                u32 w = kbase + nb*AS + ks*8 + ((lane>>3)&1)*4;
                u32 bh[4], bl[4];
                ldsm4(bh[0],bh[1],bh[2],bh[3], smb + w*4);
                ldsm4(bl[0],bl[1],bl[2],bl[3], smb + (w+KVW)*4);
                mma3(sc[2*p  ], qh, ql, bh+0, bl+0);
                mma3(sc[2*p+1], qh, ql, bh+2, bl+2);
            }
        }

        float tm0=-1e30f, tm1=-1e30f;
#pragma unroll
        for (int j=0;j<8;j++){
            tm0 = fmaxf(tm0, fmaxf(sc[j][0], sc[j][1]));
            tm1 = fmaxf(tm1, fmaxf(sc[j][2], sc[j][3]));
        }
        tm0 = fmaxf(tm0, __shfl_xor_sync(0xffffffffu, tm0, 1));
        tm0 = fmaxf(tm0, __shfl_xor_sync(0xffffffffu, tm0, 2));
        tm1 = fmaxf(tm1, __shfl_xor_sync(0xffffffffu, tm1, 1));
        tm1 = fmaxf(tm1, __shfl_xor_sync(0xffffffffu, tm1, 2));
        float mn0 = fmaxf(m0r, tm0), mn1 = fmaxf(m1r, tm1);
        float c0 = __expf(m0r - mn0), c1 = __expf(m1r - mn1);
        float rs0=0.f, rs1=0.f;
#pragma unroll
        for (int j=0;j<8;j++){
            sc[j][0]=__expf(sc[j][0]-mn0); sc[j][1]=__expf(sc[j][1]-mn0);
            sc[j][2]=__expf(sc[j][2]-mn1); sc[j][3]=__expf(sc[j][3]-mn1);
            rs0 += sc[j][0]+sc[j][1]; rs1 += sc[j][2]+sc[j][3];
        }
        rs0 += __shfl_xor_sync(0xffffffffu, rs0, 1);
        rs0 += __shfl_xor_sync(0xffffffffu, rs0, 2);
        rs1 += __shfl_xor_sync(0xffffffffu, rs1, 1);
        rs1 += __shfl_xor_sync(0xffffffffu, rs1, 2);
        l0r = l0r*c0 + rs0; l1r = l1r*c1 + rs1;
        m0r = mn0; m1r = mn1;
#pragma unroll
        for (int j=0;j<8;j++){
            oacc[j][0]*=c0; oacc[j][1]*=c0; oacc[j][2]*=c1; oacc[j][3]*=c1;
        }

#pragma unroll
        for (int s=0;s<4;s++){
            u32 ph[4], pl[4];
            split_pack(sc[2*s  ][0], sc[2*s  ][1], ph[0], pl[0]);
            split_pack(sc[2*s  ][2], sc[2*s  ][3], ph[1], pl[1]);
            split_pack(sc[2*s+1][0], sc[2*s+1][1], ph[2], pl[2]);
            split_pack(sc[2*s+1][2], sc[2*s+1][3], ph[3], pl[3]);
#pragma unroll
            for (int p=0;p<4;p++){
                int nb = p*16 + ((lane>>4)<<3) + (lane&7);
                u32 w = vbase + nb*AS + s*8 + ((lane>>3)&1)*4;
                u32 bh[4], bl[4];
                ldsm4(bh[0],bh[1],bh[2],bh[3], smb + w*4);
                ldsm4(bl[0],bl[1],bl[2],bl[3], smb + (w+KVW)*4);
                mma3(oacc[2*p  ], ph, pl, bh+0, bl+0);
                mma3(oacc[2*p+1], ph, pl, bh+2, bl+2);
            }
        }
        __syncthreads();
    }

    float inv0 = 1.f/l0r, inv1 = 1.f/l1r;
    int r0 = q0 + row + g, r1 = r0+8;
#pragma unroll
    for (int j=0;j<8;j++){
        int col = h*DKH + j*8 + t4*2;
        u32 hh, ll;
        split_pack(oacc[j][0]*inv0, oacc[j][1]*inv0, hh, ll);
        ((u32*)Ch)[(r0*NHID + col)>>1] = hh;
        ((u32*)Cl)[(r0*NHID + col)>>1] = ll;
        split_pack(oacc[j][2]*inv1, oacc[j][3]*inv1, hh, ll);
        ((u32*)Ch)[(r1*NHID + col)>>1] = hh;
        ((u32*)Cl)[(r1*NHID + col)>>1] = ll;
    }
}

// ---------------------------------------------------------------------------
extern "C" void kernel_launch(void* const* d_in, const int* in_sizes, int n_in,
                              void* d_out, int out_size)
{
    const float* Q  = (const float*)d_in[0];
    const float* K  = (const float*)d_in[1];
    const float* V  = (const float*)d_in[2];
    const float* Wq = (const float*)d_in[3];
    const float* bq = (const float*)d_in[4];
    const float* Wk = (const float*)d_in[5];
    const float* bk = (const float*)d_in[6];
    const float* Wv = (const float*)d_in[7];
    const float* bv = (const float*)d_in[8];
    const float* Wo = (const float*)d_in[9];
    const float* bo = (const float*)d_in[10];
    float* out = (float*)d_out;

    u16 *xh,*xl,*wth,*wtl,*woth,*wotl;
    u16 *qh,*ql,*kh,*kl,*vth,*vtl,*ch,*cl;
    cudaGetSymbolAddress((void**)&xh,   g_xh);
    cudaGetSymbolAddress((void**)&xl,   g_xl);
    cudaGetSymbolAddress((void**)&wth,  g_wth);
    cudaGetSymbolAddress((void**)&wtl,  g_wtl);
    cudaGetSymbolAddress((void**)&woth, g_woth);
    cudaGetSymbolAddress((void**)&wotl, g_wotl);
    cudaGetSymbolAddress((void**)&qh,   g_qh);
    cudaGetSymbolAddress((void**)&ql,   g_ql);
    cudaGetSymbolAddress((void**)&kh,   g_kh);
    cudaGetSymbolAddress((void**)&kl,   g_kl);
    cudaGetSymbolAddress((void**)&vth,  g_vth);
    cudaGetSymbolAddress((void**)&vtl,  g_vtl);
    cudaGetSymbolAddress((void**)&ch,   g_ch);
    cudaGetSymbolAddress((void**)&cl,   g_cl);

    cudaFuncSetAttribute(proj8_kernel,
                         cudaFuncAttributeMaxDynamicSharedMemorySize, GEMM8_SMEM);
    cudaFuncSetAttribute(out8_kernel,
                         cudaFuncAttributeMaxDynamicSharedMemorySize, GEMM8_SMEM);
    cudaFuncSetAttribute(attn_kernel,
                         cudaFuncAttributeMaxDynamicSharedMemorySize, ATTN_SMEM);

    // pre-passes
    asplit_kernel<<<3*SQ*DM/(256*8), 256>>>(Q, K, V, xh, xl);
    wsplit_qkv_kernel<<<dim3(32,2,48), dim3(32,32)>>>(Wq, Wk, Wv, wth, wtl);
    wsplit_wo_kernel<<<dim3(32,32), dim3(32,32)>>>(Wo, woth, wotl);

    // fused QKV projection: 64x128 tiles -> 768 CTAs (86.5% wave fill)
    dim3 pg(NH/2, SQ/64, 3);      // (8, 32, 3)
    proj8_kernel<<<pg, 256, GEMM8_SMEM>>>((u32*)xh,(u32*)xl,(u32*)wth,(u32*)wtl,
                                          bq, bk, bv,
                                          qh, ql, kh, kl, vth, vtl);

    dim3 ag(SQ/128, NH);          // (16, 16) = 256 CTAs
    attn_kernel<<<ag, 256, ATTN_SMEM>>>((u32*)qh,(u32*)ql,(u32*)kh,(u32*)kl,
                                        (u32*)vth,(u32*)vtl, ch, cl);

    // output projection: 64x128 tiles -> 256 CTAs (86.5% fill vs 43% before)
    dim3 og(DM/128, SQ/64);       // (8, 32)
    out8_kernel<<<og, 256, GEMM8_SMEM>>>((u32*)ch,(u32*)cl,(u32*)woth,(u32*)wotl,
                                         bo, out);
}

// round 15
// speedup vs baseline: 1.5846x; 1.0295x over previous
#include <cuda_runtime.h>
#include <cuda_bf16.h>

#define SQ 2048
#define DM 1024
#define NH 16
#define DKH 64
#define NHID 1024

typedef unsigned int u32;
typedef unsigned short u16;

// ---------------- scratch planes (bf16 hi/lo) ----------------
__device__ u16 g_xh[3*SQ*DM];
__device__ u16 g_xl[3*SQ*DM];
__device__ u16 g_wth[3*NH*DKH*DM];   // [(which*16+h)*64+k][d]
__device__ u16 g_wtl[3*NH*DKH*DM];
__device__ u16 g_woth[NHID*DM];      // [n][k]
__device__ u16 g_wotl[NHID*DM];
__device__ u16 g_qh[NH*SQ*DKH];
__device__ u16 g_ql[NH*SQ*DKH];
__device__ u16 g_kh[NH*SQ*DKH];
__device__ u16 g_kl[NH*SQ*DKH];
__device__ u16 g_vth[NH*DKH*SQ];     // [h][d][s]
__device__ u16 g_vtl[NH*DKH*SQ];
__device__ u16 g_ch[SQ*NHID];
__device__ u16 g_cl[SQ*NHID];

// ---------------- helpers ----------------
__device__ __forceinline__ void split1(float x, u16& h, u16& l) {
    __nv_bfloat16 hb = __float2bfloat16(x);
    h = __bfloat16_as_ushort(hb);
    l = __bfloat16_as_ushort(__float2bfloat16(x - __bfloat162float(hb)));
}
__device__ __forceinline__ void split_pack(float x0, float x1, u32& h, u32& l) {
    u16 h0,l0,h1,l1;
    split1(x0,h0,l0); split1(x1,h1,l1);
    h = ((u32)h1<<16)|h0; l = ((u32)l1<<16)|l0;
}
__device__ __forceinline__ void mma_bf16(float* c, const u32* a, const u32* b) {
    asm volatile(
      "mma.sync.aligned.m16n8k16.row.col.f32.bf16.bf16.f32 "
      "{%0,%1,%2,%3}, {%4,%5,%6,%7}, {%8,%9}, {%0,%1,%2,%3};\n"
      : "+f"(c[0]), "+f"(c[1]), "+f"(c[2]), "+f"(c[3])
      : "r"(a[0]), "r"(a[1]), "r"(a[2]), "r"(a[3]), "r"(b[0]), "r"(b[1]));
}
__device__ __forceinline__ void cp16(u32 dst_smem, const void* src) {
    asm volatile("cp.async.cg.shared.global [%0], [%1], 16;\n"
                 :: "r"(dst_smem), "l"(src));
}
__device__ __forceinline__ void cp_commit() {
    asm volatile("cp.async.commit_group;\n");
}
template<int N> __device__ __forceinline__ void cp_wait() {
    asm volatile("cp.async.wait_group %0;\n" :: "n"(N));
}
__device__ __forceinline__ void ldsm4(u32& r0, u32& r1, u32& r2, u32& r3, u32 saddr) {
    asm volatile("ldmatrix.sync.aligned.m8n8.x4.shared.b16 {%0,%1,%2,%3}, [%4];\n"
                 : "=r"(r0), "=r"(r1), "=r"(r2), "=r"(r3) : "r"(saddr));
}
// swizzled byte offset for 64B logical rows packed into 128B blocks (proven)
__device__ __forceinline__ u32 swz64(int r, int c) {
    return ((u32)(r>>1)<<7) | ((u32)(r&1)<<6) | ((u32)((c + (r>>1)) & 3)<<4);
}

// ---------------------------------------------------------------------------
// Pre-pass kernels (proven round-9 versions, unchanged)
// ---------------------------------------------------------------------------
__global__ __launch_bounds__(256) void asplit_kernel(
    const float* __restrict__ Q, const float* __restrict__ K,
    const float* __restrict__ V, u16* __restrict__ oh, u16* __restrict__ ol)
{
    size_t base = ((size_t)blockIdx.x*256 + threadIdx.x)*8;
    int which = (int)(base >> 21);
    size_t rem = base & 2097151;
    const float* in = (which==0)?Q:(which==1)?K:V;
    float4 f0 = *(const float4*)(in+rem);
    float4 f1 = *(const float4*)(in+rem+4);
    u32 h0,l0,h1,l1,h2,l2,h3,l3;
    split_pack(f0.x,f0.y,h0,l0);
    split_pack(f0.z,f0.w,h1,l1);
    split_pack(f1.x,f1.y,h2,l2);
    split_pack(f1.z,f1.w,h3,l3);
    *(uint4*)(oh + base) = make_uint4(h0,h1,h2,h3);
    *(uint4*)(ol + base) = make_uint4(l0,l1,l2,l3);
}

__global__ void wsplit_qkv_kernel(
    const float* __restrict__ Wq, const float* __restrict__ Wk,
    const float* __restrict__ Wv, u16* __restrict__ oh, u16* __restrict__ ol)
{
    __shared__ float t[32][33];
    int z = blockIdx.z, which = z>>4, h = z&15;
    const float* in = ((which==0)?Wq:(which==1)?Wk:Wv) + (size_t)h*DM*DKH;
    int d0 = blockIdx.x*32, k0 = blockIdx.y*32;
    int tx = threadIdx.x, ty = threadIdx.y;
    t[ty][tx] = in[(size_t)(d0+ty)*DKH + k0+tx];
    __syncthreads();
    float v = t[tx][ty];
    u16 hh,ll; split1(v,hh,ll);
    size_t o = ((size_t)z*DKH + k0+ty)*DM + d0+tx;
    oh[o]=hh; ol[o]=ll;
}

__global__ void wsplit_wo_kernel(
    const float* __restrict__ Wo, u16* __restrict__ oh, u16* __restrict__ ol)
{
    __shared__ float t[32][33];
    int k0 = blockIdx.x*32, n0 = blockIdx.y*32;
    int tx = threadIdx.x, ty = threadIdx.y;
    t[ty][tx] = Wo[(size_t)(k0+ty)*DM + n0+tx];
    __syncthreads();
    float v = t[tx][ty];
    u16 hh,ll; split1(v,hh,ll);
    size_t o = ((size_t)(n0+ty))*DM + k0+tx;
    oh[o]=hh; ol[o]=ll;
}

// ---------------------------------------------------------------------------
// 3-stage XOR-swizzled GEMM geometry (round-9): 128(M) x 128(N), BK=32.
// stage = Ah(8KB) Al Bh Bl = 32KB; 3 stages = 96KB. Term-phased MMA order.
// ---------------------------------------------------------------------------
#define P5_TILE 8192
#define P5_STG  (4*P5_TILE)
#define GEMM5_SMEM (3*P5_STG)
#define NKT 32

// ---- fused QKV projection ----
__global__ __launch_bounds__(256,2) void proj5_kernel(
    const u32* __restrict__ Xh, const u32* __restrict__ Xl,
    const u32* __restrict__ Wth, const u32* __restrict__ Wtl,
    const float* __restrict__ bq, const float* __restrict__ bk,
    const float* __restrict__ bv,
    u16* __restrict__ oqh, u16* __restrict__ oql,
    u16* __restrict__ okh, u16* __restrict__ okl,
    u16* __restrict__ ovh, u16* __restrict__ ovl)
{
    extern __shared__ u32 sm[];
    const u32 smb = (u32)__cvta_generic_to_shared(sm);
    const int tid = threadIdx.x, lane = tid&31, wid = tid>>5;
    const int g = lane>>2, t4 = lane&3;
    const int wm = wid>>2, wn = wid&3;       // 2x4 warps, warp tile 64x32
    const int which = blockIdx.z, head0 = blockIdx.x*2, m0 = blockIdx.y*128;

    const u32* aH = Xh + (size_t)which*(SQ*DM/2);
    const u32* aL = Xl + (size_t)which*(SQ*DM/2);
    const int zrow = (which*NH + head0)*DKH;

    float acc[4][4][4];
#pragma unroll
    for (int i=0;i<4;i++)
#pragma unroll
      for (int j=0;j<4;j++)
#pragma unroll
        for (int e=0;e<4;e++) acc[i][j][e]=0.f;

    auto issue = [&](int kt){
        if (kt < NKT){
            u32 base = (kt%3)*P5_STG;
#pragma unroll
            for (int j=0;j<8;j++){
                int i = tid + j*256;
                int tile = i>>9, rem = i&511;
                int r = rem>>2, c = rem&3;
                const u32* src;
                if      (tile==0) src = aH  + (size_t)(m0+r)*512   + kt*16 + c*4;
                else if (tile==1) src = aL  + (size_t)(m0+r)*512   + kt*16 + c*4;
                else if (tile==2) src = Wth + (size_t)(zrow+r)*512 + kt*16 + c*4;
                else              src = Wtl + (size_t)(zrow+r)*512 + kt*16 + c*4;
                cp16(smb + base + tile*P5_TILE + swz64(r,c), src);
            }
        }
        cp_commit();
    };

    issue(0); issue(1);
    for (int kt=0; kt<NKT; kt++){
        cp_wait<1>();
        __syncthreads();
        issue(kt+2);

        u32 base = smb + (kt%3)*P5_STG;
#pragma unroll
        for (int ks=0; ks<2; ks++){
            u32 bh[2][4], bl[2][4];
#pragma unroll
            for (int p=0;p<2;p++){
                int nb = wn*32 + p*16 + ((lane>>4)<<3) + (lane&7);
                int cB = ks*2 + ((lane>>3)&1);
                u32 w = base + 2*P5_TILE + swz64(nb, cB);
                ldsm4(bh[p][0],bh[p][1],bh[p][2],bh[p][3], w);
                ldsm4(bl[p][0],bl[p][1],bl[p][2],bl[p][3], w + P5_TILE);
            }
#pragma unroll
            for (int i=0;i<4;i++){
                int rowb = wm*64 + i*16 + (lane&15);
                int cA = ks*2 + (lane>>4);
                u32 w = base + swz64(rowb, cA);
                u32 ah[4], al[4];
                ldsm4(ah[0],ah[1],ah[2],ah[3], w);
                ldsm4(al[0],al[1],al[2],al[3], w + P5_TILE);
                // term-phased: same-acc reuse distance 4 (was 1).
                // Per-acc order stays hh, hl, lh -> bit-identical results.
                mma_bf16(acc[i][0], ah, bh[0]+0);
                mma_bf16(acc[i][1], ah, bh[0]+2);
                mma_bf16(acc[i][2], ah, bh[1]+0);
                mma_bf16(acc[i][3], ah, bh[1]+2);
                mma_bf16(acc[i][0], ah, bl[0]+0);
                mma_bf16(acc[i][1], ah, bl[0]+2);
                mma_bf16(acc[i][2], ah, bl[1]+0);
                mma_bf16(acc[i][3], ah, bl[1]+2);
                mma_bf16(acc[i][0], al, bh[0]+0);
                mma_bf16(acc[i][1], al, bh[0]+2);
                mma_bf16(acc[i][2], al, bh[1]+0);
                mma_bf16(acc[i][3], al, bh[1]+2);
            }
        }
    }

    // epilogue (identical to round-9)
    const float* bias = (which==0)?bq:(which==1)?bk:bv;
    const int transposed = (which==2);
    const float osc = (which==0)?0.125f:1.f;
#pragma unroll
    for (int i=0;i<4;i++){
#pragma unroll
        for (int j=0;j<4;j++){
            int r0 = m0 + wm*64 + i*16 + g;
            int r1 = r0 + 8;
            int ncol = wn*32 + j*8 + t4*2;
            int head = head0 + (ncol>>6);
            int dc = ncol & 63;
            float b0f = bias[head*DKH + dc];
            float b1f = bias[head*DKH + dc + 1];
            float v0 = (acc[i][j][0] + b0f) * osc;
            float v1 = (acc[i][j][1] + b1f) * osc;
            float v2 = (acc[i][j][2] + b0f) * osc;
            float v3 = (acc[i][j][3] + b1f) * osc;
            if (!transposed) {
                u16* outH = (which==0)?oqh:okh;
                u16* outL = (which==0)?oql:okl;
                u32 h,l;
                split_pack(v0,v1,h,l);
                ((u32*)outH)[(head*SQ + r0)*32 + (dc>>1)] = h;
                ((u32*)outL)[(head*SQ + r0)*32 + (dc>>1)] = l;
                split_pack(v2,v3,h,l);
                ((u32*)outH)[(head*SQ + r1)*32 + (dc>>1)] = h;
                ((u32*)outL)[(head*SQ + r1)*32 + (dc>>1)] = l;
            } else {
                u16 h,l;
                split1(v0,h,l); ovh[(head*DKH+dc  )*SQ + r0]=h; ovl[(head*DKH+dc  )*SQ + r0]=l;
                split1(v1,h,l); ovh[(head*DKH+dc+1)*SQ + r0]=h; ovl[(head*DKH+dc+1)*SQ + r0]=l;
                split1(v2,h,l); ovh[(head*DKH+dc  )*SQ + r1]=h; ovl[(head*DKH+dc  )*SQ + r1]=l;
                split1(v3,h,l); ovh[(head*DKH+dc+1)*SQ + r1]=h; ovl[(head*DKH+dc+1)*SQ + r1]=l;
            }
        }
    }
}

// ---- output projection, same structure ----
__global__ __launch_bounds__(256,2) void out5_kernel(
    const u32* __restrict__ Ah, const u32* __restrict__ Al,
    const u32* __restrict__ Bh, const u32* __restrict__ Bl,
    const float* __restrict__ bias, float* __restrict__ C)
{
    extern __shared__ u32 sm[];
    const u32 smb = (u32)__cvta_generic_to_shared(sm);
    const int tid = threadIdx.x, lane = tid&31, wid = tid>>5;
    const int g = lane>>2, t4 = lane&3;
    const int wm = wid>>2, wn = wid&3;
    const int n0 = blockIdx.x*128, m0 = blockIdx.y*128;

    float acc[4][4][4];
#pragma unroll
    for (int i=0;i<4;i++)
#pragma unroll
      for (int j=0;j<4;j++)
#pragma unroll
        for (int e=0;e<4;e++) acc[i][j][e]=0.f;

    auto issue = [&](int kt){
        if (kt < NKT){
            u32 base = (kt%3)*P5_STG;
#pragma unroll
            for (int j=0;j<8;j++){
                int i = tid + j*256;
                int tile = i>>9, rem = i&511;
                int r = rem>>2, c = rem&3;
                const u32* src;
                if      (tile==0) src = Ah + (size_t)(m0+r)*512 + kt*16 + c*4;
                else if (tile==1) src = Al + (size_t)(m0+r)*512 + kt*16 + c*4;
                else if (tile==2) src = Bh + (size_t)(n0+r)*512 + kt*16 + c*4;
                else              src = Bl + (size_t)(n0+r)*512 + kt*16 + c*4;
                cp16(smb + base + tile*P5_TILE + swz64(r,c), src);
            }
        }
        cp_commit();
    };

    issue(0); issue(1);
    for (int kt=0; kt<NKT; kt++){
        cp_wait<1>();
        __syncthreads();
        issue(kt+2);

        u32 base = smb + (kt%3)*P5_STG;
#pragma unroll
        for (int ks=0; ks<2; ks++){
            u32 bh[2][4], bl[2][4];
#pragma unroll
            for (int p=0;p<2;p++){
                int nb = wn*32 + p*16 + ((lane>>4)<<3) + (lane&7);
                int cB = ks*2 + ((lane>>3)&1);
                u32 w = base + 2*P5_TILE + swz64(nb, cB);
                ldsm4(bh[p][0],bh[p][1],bh[p][2],bh[p][3], w);
                ldsm4(bl[p][0],bl[p][1],bl[p][2],bl[p][3], w + P5_TILE);
            }
#pragma unroll
            for (int i=0;i<4;i++){
                int rowb = wm*64 + i*16 + (lane&15);
                int cA = ks*2 + (lane>>4);
                u32 w = base + swz64(rowb, cA);
                u32 ah[4], al[4];
                ldsm4(ah[0],ah[1],ah[2],ah[3], w);
                ldsm4(al[0],al[1],al[2],al[3], w + P5_TILE);
                mma_bf16(acc[i][0], ah, bh[0]+0);
                mma_bf16(acc[i][1], ah, bh[0]+2);
                mma_bf16(acc[i][2], ah, bh[1]+0);
                mma_bf16(acc[i][3], ah, bh[1]+2);
                mma_bf16(acc[i][0], ah, bl[0]+0);
                mma_bf16(acc[i][1], ah, bl[0]+2);
                mma_bf16(acc[i][2], ah, bl[1]+0);
                mma_bf16(acc[i][3], ah, bl[1]+2);
                mma_bf16(acc[i][0], al, bh[0]+0);
                mma_bf16(acc[i][1], al, bh[0]+2);
                mma_bf16(acc[i][2], al, bh[1]+0);
                mma_bf16(acc[i][3], al, bh[1]+2);
            }
        }
    }

#pragma unroll
    for (int i=0;i<4;i++){
#pragma unroll
        for (int j=0;j<4;j++){
            int r0 = m0 + wm*64 + i*16 + g;
            int r1 = r0 + 8;
            int col = n0 + wn*32 + j*8 + t4*2;
            C[(size_t)r0*DM + col    ] = acc[i][j][0] + bias[col];
            C[(size_t)r0*DM + col + 1] = acc[i][j][1] + bias[col+1];
            C[(size_t)r1*DM + col    ] = acc[i][j][2] + bias[col];
            C[(size_t)r1*DM + col + 1] = acc[i][j][3] + bias[col+1];
        }
    }
}

// ---------------------------------------------------------------------------
// Flash attention: round-9 structure, pair-processed term-phased MMAs
// (same-acc distance 4 in QK and PV; per-acc term order preserved).
// ---------------------------------------------------------------------------
#define AS 36
#define KVW (64*AS)
#define ATTN_WORDS (2*128*AS + 2*4*KVW)
#define ATTN_SMEM (ATTN_WORDS*4)

__global__ __launch_bounds__(256,2) void attn_kernel(
    const u32* __restrict__ Qh, const u32* __restrict__ Ql,
    const u32* __restrict__ Kh, const u32* __restrict__ Kl,
    const u32* __restrict__ Vh, const u32* __restrict__ Vl,
    u16* __restrict__ Ch, u16* __restrict__ Cl)
{
    extern __shared__ u32 sm[];
    const u32 smb = (u32)__cvta_generic_to_shared(sm);

    const int tid = threadIdx.x, lane = tid&31, wid = tid>>5;
    const int g = lane>>2, t4 = lane&3;
    const int h = blockIdx.y, q0 = blockIdx.x*128;
    const int row = wid*16;

#pragma unroll
    for (int j=0;j<8;j++){
        int i = tid + j*256;
        int plane = i>>10, rem = i&1023;
        int r = rem>>3, c = rem&7;
        const u32* src = (plane ? Ql : Qh) + ((size_t)(h*SQ + q0 + r))*32 + c*4;
        cp16(smb + ((plane ? 128*AS : 0) + r*AS + c*4)*4, src);
    }
    cp_commit();

    auto issueKV = [&](int t, int st){
        u32 base = 2*128*AS + st*4*KVW;
#pragma unroll
        for (int j=0;j<2;j++){
            int i = tid + j*256;
            int r = i>>3, c = i&7;
            cp16(smb + (base +           r*AS + c*4)*4, Kh + ((size_t)(h*SQ + t*64 + r))*32 + c*4);
            cp16(smb + (base +   KVW +   r*AS + c*4)*4, Kl + ((size_t)(h*SQ + t*64 + r))*32 + c*4);
            cp16(smb + (base + 2*KVW +   r*AS + c*4)*4, Vh + ((size_t)(h*DKH + r))*1024 + t*32 + c*4);
            cp16(smb + (base + 3*KVW +   r*AS + c*4)*4, Vl + ((size_t)(h*DKH + r))*1024 + t*32 + c*4);
        }
        cp_commit();
    };
    issueKV(0,0);

    float oacc[8][4];
#pragma unroll
    for (int j=0;j<8;j++)
#pragma unroll
        for (int e=0;e<4;e++) oacc[j][e]=0.f;
    float m0r=-1e30f, m1r=-1e30f, l0r=0.f, l1r=0.f;

    for (int t=0; t<SQ/64; t++){
        const int st = t & 1;
        if (t+1 < SQ/64) { issueKV(t+1, st^1); cp_wait<1>(); }
        else cp_wait<0>();
        __syncthreads();

        u32 kbase = 2*128*AS + st*4*KVW;
        u32 vbase = kbase + 2*KVW;

        // scores: pair-processed p, term-phased (distance 4)
        float sc[8][4];
#pragma unroll
        for (int j=0;j<8;j++)
#pragma unroll
            for (int e=0;e<4;e++) sc[j][e]=0.f;
#pragma unroll
        for (int ks=0;ks<4;ks++){
            u32 qh[4], ql[4];
            int rowb = row + (lane&15);
            u32 wq = rowb*AS + ks*8 + (lane>>4)*4;
            ldsm4(qh[0],qh[1],qh[2],qh[3], smb + wq*4);
            ldsm4(ql[0],ql[1],ql[2],ql[3], smb + (wq + 128*AS)*4);
#pragma unroll
            for (int pp=0;pp<2;pp++){
                int nb0 = (2*pp  )*16 + ((lane>>4)<<3) + (lane&7);
                int nb1 = (2*pp+1)*16 + ((lane>>4)<<3) + (lane&7);
                u32 w0 = kbase + nb0*AS + ks*8 + ((lane>>3)&1)*4;
                u32 w1 = kbase + nb1*AS + ks*8 + ((lane>>3)&1)*4;
                u32 bh0[4], bl0[4], bh1[4], bl1[4];
                ldsm4(bh0[0],bh0[1],bh0[2],bh0[3], smb + w0*4);
                ldsm4(bl0[0],bl0[1],bl0[2],bl0[3], smb + (w0+KVW)*4);
                ldsm4(bh1[0],bh1[1],bh1[2],bh1[3], smb + w1*4);
                ldsm4(bl1[0],bl1[1],bl1[2],bl1[3], smb + (w1+KVW)*4);
                float* c0 = sc[4*pp+0]; float* c1 = sc[4*pp+1];
                float* c2 = sc[4*pp+2]; float* c3 = sc[4*pp+3];
                mma_bf16(c0, qh, bh0+0); mma_bf16(c1, qh, bh0+2);
                mma_bf16(c2, qh, bh1+0); mma_bf16(c3, qh, bh1+2);
                mma_bf16(c0, qh, bl0+0); mma_bf16(c1, qh, bl0+2);
                mma_bf16(c2, qh, bl1+0); mma_bf16(c3, qh, bl1+2);
                mma_bf16(c0, ql, bh0+0); mma_bf16(c1, ql, bh0+2);
                mma_bf16(c2, ql, bh1+0); mma_bf16(c3, ql, bh1+2);
            }
        }

        // online softmax (Q pre-scaled by 0.125)
        float tm0=-1e30f, tm1=-1e30f;
#pragma unroll
        for (int j=0;j<8;j++){
            tm0 = fmaxf(tm0, fmaxf(sc[j][0], sc[j][1]));
            tm1 = fmaxf(tm1, fmaxf(sc[j][2], sc[j][3]));
        }
        tm0 = fmaxf(tm0, __shfl_xor_sync(0xffffffffu, tm0, 1));
        tm0 = fmaxf(tm0, __shfl_xor_sync(0xffffffffu, tm0, 2));
        tm1 = fmaxf(tm1, __shfl_xor_sync(0xffffffffu, tm1, 1));
        tm1 = fmaxf(tm1, __shfl_xor_sync(0xffffffffu, tm1, 2));
        float mn0 = fmaxf(m0r, tm0), mn1 = fmaxf(m1r, tm1);
        float c0s = __expf(m0r - mn0), c1s = __expf(m1r - mn1);
        float rs0=0.f, rs1=0.f;
#pragma unroll
        for (int j=0;j<8;j++){
            sc[j][0]=__expf(sc[j][0]-mn0); sc[j][1]=__expf(sc[j][1]-mn0);
            sc[j][2]=__expf(sc[j][2]-mn1); sc[j][3]=__expf(sc[j][3]-mn1);
            rs0 += sc[j][0]+sc[j][1]; rs1 += sc[j][2]+sc[j][3];
        }
        rs0 += __shfl_xor_sync(0xffffffffu, rs0, 1);
        rs0 += __shfl_xor_sync(0xffffffffu, rs0, 2);
        rs1 += __shfl_xor_sync(0xffffffffu, rs1, 1);
        rs1 += __shfl_xor_sync(0xffffffffu, rs1, 2);
        l0r = l0r*c0s + rs0; l1r = l1r*c1s + rs1;
        m0r = mn0; m1r = mn1;
#pragma unroll
        for (int j=0;j<8;j++){
            oacc[j][0]*=c0s; oacc[j][1]*=c0s; oacc[j][2]*=c1s; oacc[j][3]*=c1s;
        }

        // PV: pair-processed, term-phased (distance 4)
#pragma unroll
        for (int s=0;s<4;s++){
            u32 ph[4], pl[4];
            split_pack(sc[2*s  ][0], sc[2*s  ][1], ph[0], pl[0]);
            split_pack(sc[2*s  ][2], sc[2*s  ][3], ph[1], pl[1]);
            split_pack(sc[2*s+1][0], sc[2*s+1][1], ph[2], pl[2]);
            split_pack(sc[2*s+1][2], sc[2*s+1][3], ph[3], pl[3]);
#pragma unroll
            for (int pp=0;pp<2;pp++){
                int nb0 = (2*pp  )*16 + ((lane>>4)<<3) + (lane&7);
                int nb1 = (2*pp+1)*16 + ((lane>>4)<<3) + (lane&7);
                u32 w0 = vbase + nb0*AS + s*8 + ((lane>>3)&1)*4;
                u32 w1 = vbase + nb1*AS + s*8 + ((lane>>3)&1)*4;
                u32 bh0[4], bl0[4], bh1[4], bl1[4];
                ldsm4(bh0[0],bh0[1],bh0[2],bh0[3], smb + w0*4);
                ldsm4(bl0[0],bl0[1],bl0[2],bl0[3], smb + (w0+KVW)*4);
                ldsm4(bh1[0],bh1[1],bh1[2],bh1[3], smb + w1*4);
                ldsm4(bl1[0],bl1[1],bl1[2],bl1[3], smb + (w1+KVW)*4);
                float* c0 = oacc[4*pp+0]; float* c1 = oacc[4*pp+1];
                float* c2 = oacc[4*pp+2]; float* c3 = oacc[4*pp+3];
                mma_bf16(c0, ph, bh0+0); mma_bf16(c1, ph, bh0+2);
                mma_bf16(c2, ph, bh1+0); mma_bf16(c3, ph, bh1+2);
                mma_bf16(c0, ph, bl0+0); mma_bf16(c1, ph, bl0+2);
                mma_bf16(c2, ph, bl1+0); mma_bf16(c3, ph, bl1+2);
                mma_bf16(c0, pl, bh0+0); mma_bf16(c1, pl, bh0+2);
                mma_bf16(c2, pl, bh1+0); mma_bf16(c3, pl, bh1+2);
            }
        }
        __syncthreads();
    }

    float inv0 = 1.f/l0r, inv1 = 1.f/l1r;
    int r0 = q0 + row + g, r1 = r0+8;
#pragma unroll
    for (int j=0;j<8;j++){
        int col = h*DKH + j*8 + t4*2;
        u32 hh, ll;
        split_pack(oacc[j][0]*inv0, oacc[j][1]*inv0, hh, ll);
        ((u32*)Ch)[(r0*NHID + col)>>1] = hh;
        ((u32*)Cl)[(r0*NHID + col)>>1] = ll;
        split_pack(oacc[j][2]*inv1, oacc[j][3]*inv1, hh, ll);
        ((u32*)Ch)[(r1*NHID + col)>>1] = hh;
        ((u32*)Cl)[(r1*NHID + col)>>1] = ll;
    }
}

// ---------------------------------------------------------------------------
extern "C" void kernel_launch(void* const* d_in, const int* in_sizes, int n_in,
                              void* d_out, int out_size)
{
    const float* Q  = (const float*)d_in[0];
    const float* K  = (const float*)d_in[1];
    const float* V  = (const float*)d_in[2];
    const float* Wq = (const float*)d_in[3];
    const float* bq = (const float*)d_in[4];
    const float* Wk = (const float*)d_in[5];
    const float* bk = (const float*)d_in[6];
    const float* Wv = (const float*)d_in[7];
    const float* bv = (const float*)d_in[8];
    const float* Wo = (const float*)d_in[9];
    const float* bo = (const float*)d_in[10];
    float* out = (float*)d_out;

    u16 *xh,*xl,*wth,*wtl,*woth,*wotl;
    u16 *qh,*ql,*kh,*kl,*vth,*vtl,*ch,*cl;
    cudaGetSymbolAddress((void**)&xh,   g_xh);
    cudaGetSymbolAddress((void**)&xl,   g_xl);
    cudaGetSymbolAddress((void**)&wth,  g_wth);
    cudaGetSymbolAddress((void**)&wtl,  g_wtl);
    cudaGetSymbolAddress((void**)&woth, g_woth);
    cudaGetSymbolAddress((void**)&wotl, g_wotl);
    cudaGetSymbolAddress((void**)&qh,   g_qh);
    cudaGetSymbolAddress((void**)&ql,   g_ql);
    cudaGetSymbolAddress((void**)&kh,   g_kh);
    cudaGetSymbolAddress((void**)&kl,   g_kl);
    cudaGetSymbolAddress((void**)&vth,  g_vth);
    cudaGetSymbolAddress((void**)&vtl,  g_vtl);
    cudaGetSymbolAddress((void**)&ch,   g_ch);
    cudaGetSymbolAddress((void**)&cl,   g_cl);

    cudaFuncSetAttribute(proj5_kernel,
                         cudaFuncAttributeMaxDynamicSharedMemorySize, GEMM5_SMEM);
    cudaFuncSetAttribute(out5_kernel,
                         cudaFuncAttributeMaxDynamicSharedMemorySize, GEMM5_SMEM);
    cudaFuncSetAttribute(attn_kernel,
                         cudaFuncAttributeMaxDynamicSharedMemorySize, ATTN_SMEM);

    // pre-passes
    asplit_kernel<<<3*SQ*DM/(256*8), 256>>>(Q, K, V, xh, xl);
    wsplit_qkv_kernel<<<dim3(32,2,48), dim3(32,32)>>>(Wq, Wk, Wv, wth, wtl);
    wsplit_wo_kernel<<<dim3(32,32), dim3(32,32)>>>(Wo, woth, wotl);

    dim3 pg(NH/2, SQ/128, 3);     // (8, 16, 3)
    proj5_kernel<<<pg, 256, GEMM5_SMEM>>>((u32*)xh,(u32*)xl,(u32*)wth,(u32*)wtl,
                                          bq, bk, bv,
                                          qh, ql, kh, kl, vth, vtl);

    dim3 ag(SQ/128, NH);          // (16, 16)
    attn_kernel<<<ag, 256, ATTN_SMEM>>>((u32*)qh,(u32*)ql,(u32*)kh,(u32*)kl,
                                        (u32*)vth,(u32*)vtl, ch, cl);

    dim3 og(DM/128, SQ/128);      // (8, 16)
    out5_kernel<<<og, 256, GEMM5_SMEM>>>((u32*)ch,(u32*)cl,(u32*)woth,(u32*)wotl,
                                         bo, out);
}

// round 16
// speedup vs baseline: 1.6703x; 1.0541x over previous
#include <cuda_runtime.h>
#include <cuda_bf16.h>

#define SQ 2048
#define DM 1024
#define NH 16
#define DKH 64
#define NHID 1024

typedef unsigned int u32;
typedef unsigned short u16;

// ---------------- scratch planes (bf16 hi/lo) ----------------
__device__ u16 g_xh[3*SQ*DM];
__device__ u16 g_xl[3*SQ*DM];
__device__ u16 g_wth[3*NH*DKH*DM];   // [(which*16+h)*64+k][d]
__device__ u16 g_wtl[3*NH*DKH*DM];
__device__ u16 g_woth[NHID*DM];      // [n][k]
__device__ u16 g_wotl[NHID*DM];
__device__ u16 g_qh[NH*SQ*DKH];
__device__ u16 g_ql[NH*SQ*DKH];
__device__ u16 g_kh[NH*SQ*DKH];
__device__ u16 g_kl[NH*SQ*DKH];
__device__ u16 g_vth[NH*DKH*SQ];     // [h][d][s]
__device__ u16 g_vtl[NH*DKH*SQ];
__device__ u16 g_ch[SQ*NHID];
__device__ u16 g_cl[SQ*NHID];

// ---------------- helpers ----------------
__device__ __forceinline__ void split1(float x, u16& h, u16& l) {
    __nv_bfloat16 hb = __float2bfloat16(x);
    h = __bfloat16_as_ushort(hb);
    l = __bfloat16_as_ushort(__float2bfloat16(x - __bfloat162float(hb)));
}
__device__ __forceinline__ void split_pack(float x0, float x1, u32& h, u32& l) {
    u16 h0,l0,h1,l1;
    split1(x0,h0,l0); split1(x1,h1,l1);
    h = ((u32)h1<<16)|h0; l = ((u32)l1<<16)|l0;
}
__device__ __forceinline__ void mma_bf16(float* c, const u32* a, const u32* b) {
    asm volatile(
      "mma.sync.aligned.m16n8k16.row.col.f32.bf16.bf16.f32 "
      "{%0,%1,%2,%3}, {%4,%5,%6,%7}, {%8,%9}, {%0,%1,%2,%3};\n"
      : "+f"(c[0]), "+f"(c[1]), "+f"(c[2]), "+f"(c[3])
      : "r"(a[0]), "r"(a[1]), "r"(a[2]), "r"(a[3]), "r"(b[0]), "r"(b[1]));
}
__device__ __forceinline__ void mma3(float* c, const u32* ah, const u32* al,
                                     const u32* bh, const u32* bl) {
    mma_bf16(c, ah, bh);
    mma_bf16(c, ah, bl);
    mma_bf16(c, al, bh);
}
__device__ __forceinline__ void cp16(u32 dst_smem, const void* src) {
    asm volatile("cp.async.cg.shared.global [%0], [%1], 16;\n"
                 :: "r"(dst_smem), "l"(src));
}
__device__ __forceinline__ void cp_commit() {
    asm volatile("cp.async.commit_group;\n");
}
template<int N> __device__ __forceinline__ void cp_wait() {
    asm volatile("cp.async.wait_group %0;\n" :: "n"(N));
}
__device__ __forceinline__ void ldsm4(u32& r0, u32& r1, u32& r2, u32& r3, u32 saddr) {
    asm volatile("ldmatrix.sync.aligned.m8n8.x4.shared.b16 {%0,%1,%2,%3}, [%4];\n"
                 : "=r"(r0), "=r"(r1), "=r"(r2), "=r"(r3) : "r"(saddr));
}
// swizzled byte offset for 64B logical rows packed into 128B blocks (proven)
__device__ __forceinline__ u32 swz64(int r, int c) {
    return ((u32)(r>>1)<<7) | ((u32)(r&1)<<6) | ((u32)((c + (r>>1)) & 3)<<4);
}

// ---------------------------------------------------------------------------
// Fused pre-pass: ONE launch.
//   blocks [0, 3072)      : split activations (identical math to asplit)
//   blocks [3072, 6144)   : transpose+split QKV weights (vectorized)
//   blocks [6144, 7168)   : transpose+split Wo (vectorized)
// ---------------------------------------------------------------------------
__global__ __launch_bounds__(256) void prepass_kernel(
    const float* __restrict__ Q, const float* __restrict__ K,
    const float* __restrict__ V,
    const float* __restrict__ Wq, const float* __restrict__ Wk,
    const float* __restrict__ Wv, const float* __restrict__ Wo,
    u16* __restrict__ xh, u16* __restrict__ xl,
    u16* __restrict__ wth, u16* __restrict__ wtl,
    u16* __restrict__ woth, u16* __restrict__ wotl)
{
    __shared__ float t[32][33];
    int b = blockIdx.x;
    if (b < 3072) {
        // ---- activation split: 8 floats/thread ----
        size_t base = ((size_t)b*256 + threadIdx.x)*8;
        int which = (int)(base >> 21);
        size_t rem = base & 2097151;
        const float* in = (which==0)?Q:(which==1)?K:V;
        float4 f0 = *(const float4*)(in+rem);
        float4 f1 = *(const float4*)(in+rem+4);
        u32 h0,l0,h1,l1,h2,l2,h3,l3;
        split_pack(f0.x,f0.y,h0,l0);
        split_pack(f0.z,f0.w,h1,l1);
        split_pack(f1.x,f1.y,h2,l2);
        split_pack(f1.z,f1.w,h3,l3);
        *(uint4*)(xh + base) = make_uint4(h0,h1,h2,h3);
        *(uint4*)(xl + base) = make_uint4(l0,l1,l2,l3);
    } else if (b < 6144) {
        // ---- QKV weight transpose+split: 32x32 tile, 4 elem/thread ----
        int bb = b - 3072;                 // 0..3071
        int z = bb >> 6;                   // 0..47
        int rem = bb & 63;
        int d0 = (rem >> 1) * 32;          // 0..992
        int k0 = (rem & 1) * 32;           // 0 or 32
        int which = z>>4, h = z&15;
        const float* in = ((which==0)?Wq:(which==1)?Wk:Wv) + (size_t)h*DM*DKH;
        int row = threadIdx.x >> 3, c4 = threadIdx.x & 7;
        float4 v4 = *(const float4*)(in + (size_t)(d0+row)*DKH + k0 + c4*4);
        t[row][c4*4+0] = v4.x; t[row][c4*4+1] = v4.y;
        t[row][c4*4+2] = v4.z; t[row][c4*4+3] = v4.w;
        __syncthreads();
        // thread writes out row (k = k0+row), cols d0+c4*4..+3
        u16 hh[4], ll[4];
#pragma unroll
        for (int i=0;i<4;i++) split1(t[c4*4+i][row], hh[i], ll[i]);
        size_t ofs = ((size_t)z*DKH + k0+row)*DM + d0 + c4*4;
        *(uint2*)(wth + ofs) = make_uint2(((u32)hh[1]<<16)|hh[0], ((u32)hh[3]<<16)|hh[2]);
        *(uint2*)(wtl + ofs) = make_uint2(((u32)ll[1]<<16)|ll[0], ((u32)ll[3]<<16)|ll[2]);
    } else {
        // ---- Wo transpose+split: 32x32 tile, 4 elem/thread ----
        int bb = b - 6144;                 // 0..1023
        int n0 = (bb >> 5) * 32;
        int k0 = (bb & 31) * 32;
        int row = threadIdx.x >> 3, c4 = threadIdx.x & 7;
        float4 v4 = *(const float4*)(Wo + (size_t)(k0+row)*DM + n0 + c4*4);
        t[row][c4*4+0] = v4.x; t[row][c4*4+1] = v4.y;
        t[row][c4*4+2] = v4.z; t[row][c4*4+3] = v4.w;
        __syncthreads();
        u16 hh[4], ll[4];
#pragma unroll
        for (int i=0;i<4;i++) split1(t[c4*4+i][row], hh[i], ll[i]);
        size_t ofs = ((size_t)(n0+row))*DM + k0 + c4*4;
        *(uint2*)(woth + ofs) = make_uint2(((u32)hh[1]<<16)|hh[0], ((u32)hh[3]<<16)|hh[2]);
        *(uint2*)(wotl + ofs) = make_uint2(((u32)ll[1]<<16)|ll[0], ((u32)ll[3]<<16)|ll[2]);
    }
}

// ---------------------------------------------------------------------------
// 3-stage XOR-swizzled GEMM geometry (round-9 winner, unchanged): 128x128, BK=32
// ---------------------------------------------------------------------------
#define P5_TILE 8192
#define P5_STG  (4*P5_TILE)
#define GEMM5_SMEM (3*P5_STG)
#define NKT 32

__global__ __launch_bounds__(256,2) void proj5_kernel(
    const u32* __restrict__ Xh, const u32* __restrict__ Xl,
    const u32* __restrict__ Wth, const u32* __restrict__ Wtl,
    const float* __restrict__ bq, const float* __restrict__ bk,
    const float* __restrict__ bv,
    u16* __restrict__ oqh, u16* __restrict__ oql,
    u16* __restrict__ okh, u16* __restrict__ okl,
    u16* __restrict__ ovh, u16* __restrict__ ovl)
{
    extern __shared__ u32 sm[];
    const u32 smb = (u32)__cvta_generic_to_shared(sm);
    const int tid = threadIdx.x, lane = tid&31, wid = tid>>5;
    const int g = lane>>2, t4 = lane&3;
    const int wm = wid>>2, wn = wid&3;       // 2x4 warps, warp tile 64x32
    const int which = blockIdx.z, head0 = blockIdx.x*2, m0 = blockIdx.y*128;

    const u32* aH = Xh + (size_t)which*(SQ*DM/2);
    const u32* aL = Xl + (size_t)which*(SQ*DM/2);
    const int zrow = (which*NH + head0)*DKH;

    float acc[4][4][4];
#pragma unroll
    for (int i=0;i<4;i++)
#pragma unroll
      for (int j=0;j<4;j++)
#pragma unroll
        for (int e=0;e<4;e++) acc[i][j][e]=0.f;

    auto issue = [&](int kt){
        if (kt < NKT){
            u32 base = (kt%3)*P5_STG;
#pragma unroll
            for (int j=0;j<8;j++){
                int i = tid + j*256;
                int tile = i>>9, rem = i&511;
                int r = rem>>2, c = rem&3;
                const u32* src;
                if      (tile==0) src = aH  + (size_t)(m0+r)*512   + kt*16 + c*4;
                else if (tile==1) src = aL  + (size_t)(m0+r)*512   + kt*16 + c*4;
                else if (tile==2) src = Wth + (size_t)(zrow+r)*512 + kt*16 + c*4;
                else              src = Wtl + (size_t)(zrow+r)*512 + kt*16 + c*4;
                cp16(smb + base + tile*P5_TILE + swz64(r,c), src);
            }
        }
        cp_commit();
    };

    issue(0); issue(1);
    for (int kt=0; kt<NKT; kt++){
        cp_wait<1>();
        __syncthreads();
        issue(kt+2);

        u32 base = smb + (kt%3)*P5_STG;
#pragma unroll
        for (int ks=0; ks<2; ks++){
            u32 bh[2][4], bl[2][4];
#pragma unroll
            for (int p=0;p<2;p++){
                int nb = wn*32 + p*16 + ((lane>>4)<<3) + (lane&7);
                int cB = ks*2 + ((lane>>3)&1);
                u32 w = base + 2*P5_TILE + swz64(nb, cB);
                ldsm4(bh[p][0],bh[p][1],bh[p][2],bh[p][3], w);
                ldsm4(bl[p][0],bl[p][1],bl[p][2],bl[p][3], w + P5_TILE);
            }
#pragma unroll
            for (int i=0;i<4;i++){
                int rowb = wm*64 + i*16 + (lane&15);
                int cA = ks*2 + (lane>>4);
                u32 w = base + swz64(rowb, cA);
                u32 ah[4], al[4];
                ldsm4(ah[0],ah[1],ah[2],ah[3], w);
                ldsm4(al[0],al[1],al[2],al[3], w + P5_TILE);
#pragma unroll
                for (int p=0;p<2;p++){
                    mma3(acc[i][2*p  ], ah, al, bh[p]+0, bl[p]+0);
                    mma3(acc[i][2*p+1], ah, al, bh[p]+2, bl[p]+2);
                }
            }
        }
    }

    // epilogue
    const float* bias = (which==0)?bq:(which==1)?bk:bv;
    const int transposed = (which==2);
    const float osc = (which==0)?0.125f:1.f;
#pragma unroll
    for (int i=0;i<4;i++){
#pragma unroll
        for (int j=0;j<4;j++){
            int r0 = m0 + wm*64 + i*16 + g;
            int r1 = r0 + 8;
            int ncol = wn*32 + j*8 + t4*2;
            int head = head0 + (ncol>>6);
            int dc = ncol & 63;
            float b0f = bias[head*DKH + dc];
            float b1f = bias[head*DKH + dc + 1];
            float v0 = (acc[i][j][0] + b0f) * osc;
            float v1 = (acc[i][j][1] + b1f) * osc;
            float v2 = (acc[i][j][2] + b0f) * osc;
            float v3 = (acc[i][j][3] + b1f) * osc;
            if (!transposed) {
                u16* outH = (which==0)?oqh:okh;
                u16* outL = (which==0)?oql:okl;
                u32 h,l;
                split_pack(v0,v1,h,l);
                ((u32*)outH)[(head*SQ + r0)*32 + (dc>>1)] = h;
                ((u32*)outL)[(head*SQ + r0)*32 + (dc>>1)] = l;
                split_pack(v2,v3,h,l);
                ((u32*)outH)[(head*SQ + r1)*32 + (dc>>1)] = h;
                ((u32*)outL)[(head*SQ + r1)*32 + (dc>>1)] = l;
            } else {
                u16 h,l;
                split1(v0,h,l); ovh[(head*DKH+dc  )*SQ + r0]=h; ovl[(head*DKH+dc  )*SQ + r0]=l;
                split1(v1,h,l); ovh[(head*DKH+dc+1)*SQ + r0]=h; ovl[(head*DKH+dc+1)*SQ + r0]=l;
                split1(v2,h,l); ovh[(head*DKH+dc  )*SQ + r1]=h; ovl[(head*DKH+dc  )*SQ + r1]=l;
                split1(v3,h,l); ovh[(head*DKH+dc+1)*SQ + r1]=h; ovl[(head*DKH+dc+1)*SQ + r1]=l;
            }
        }
    }
}

__global__ __launch_bounds__(256,2) void out5_kernel(
    const u32* __restrict__ Ah, const u32* __restrict__ Al,
    const u32* __restrict__ Bh, const u32* __restrict__ Bl,
    const float* __restrict__ bias, float* __restrict__ C)
{
    extern __shared__ u32 sm[];
    const u32 smb = (u32)__cvta_generic_to_shared(sm);
    const int tid = threadIdx.x, lane = tid&31, wid = tid>>5;
    const int g = lane>>2, t4 = lane&3;
    const int wm = wid>>2, wn = wid&3;
    const int n0 = blockIdx.x*128, m0 = blockIdx.y*128;

    float acc[4][4][4];
#pragma unroll
    for (int i=0;i<4;i++)
#pragma unroll
      for (int j=0;j<4;j++)
#pragma unroll
        for (int e=0;e<4;e++) acc[i][j][e]=0.f;

    auto issue = [&](int kt){
        if (kt < NKT){
            u32 base = (kt%3)*P5_STG;
#pragma unroll
            for (int j=0;j<8;j++){
                int i = tid + j*256;
                int tile = i>>9, rem = i&511;
                int r = rem>>2, c = rem&3;
                const u32* src;
                if      (tile==0) src = Ah + (size_t)(m0+r)*512 + kt*16 + c*4;
                else if (tile==1) src = Al + (size_t)(m0+r)*512 + kt*16 + c*4;
                else if (tile==2) src = Bh + (size_t)(n0+r)*512 + kt*16 + c*4;
                else              src = Bl + (size_t)(n0+r)*512 + kt*16 + c*4;
                cp16(smb + base + tile*P5_TILE + swz64(r,c), src);
            }
        }
        cp_commit();
    };

    issue(0); issue(1);
    for (int kt=0; kt<NKT; kt++){
        cp_wait<1>();
        __syncthreads();
        issue(kt+2);

        u32 base = smb + (kt%3)*P5_STG;
#pragma unroll
        for (int ks=0; ks<2; ks++){
            u32 bh[2][4], bl[2][4];
#pragma unroll
            for (int p=0;p<2;p++){
                int nb = wn*32 + p*16 + ((lane>>4)<<3) + (lane&7);
                int cB = ks*2 + ((lane>>3)&1);
                u32 w = base + 2*P5_TILE + swz64(nb, cB);
                ldsm4(bh[p][0],bh[p][1],bh[p][2],bh[p][3], w);
                ldsm4(bl[p][0],bl[p][1],bl[p][2],bl[p][3], w + P5_TILE);
            }
#pragma unroll
            for (int i=0;i<4;i++){
                int rowb = wm*64 + i*16 + (lane&15);
                int cA = ks*2 + (lane>>4);
                u32 w = base + swz64(rowb, cA);
                u32 ah[4], al[4];
                ldsm4(ah[0],ah[1],ah[2],ah[3], w);
                ldsm4(al[0],al[1],al[2],al[3], w + P5_TILE);
#pragma unroll
                for (int p=0;p<2;p++){
                    mma3(acc[i][2*p  ], ah, al, bh[p]+0, bl[p]+0);
                    mma3(acc[i][2*p+1], ah, al, bh[p]+2, bl[p]+2);
                }
            }
        }
    }

#pragma unroll
    for (int i=0;i<4;i++){
#pragma unroll
        for (int j=0;j<4;j++){
            int r0 = m0 + wm*64 + i*16 + g;
            int r1 = r0 + 8;
            int col = n0 + wn*32 + j*8 + t4*2;
            C[(size_t)r0*DM + col    ] = acc[i][j][0] + bias[col];
            C[(size_t)r0*DM + col + 1] = acc[i][j][1] + bias[col+1];
            C[(size_t)r1*DM + col    ] = acc[i][j][2] + bias[col];
            C[(size_t)r1*DM + col + 1] = acc[i][j][3] + bias[col+1];
        }
    }
}

// ---------------------------------------------------------------------------
// Flash attention (round-9 winner, unchanged)
// ---------------------------------------------------------------------------
#define AS 36
#define KVW (64*AS)
#define ATTN_WORDS (2*128*AS + 2*4*KVW)
#define ATTN_SMEM (ATTN_WORDS*4)

__global__ __launch_bounds__(256,2) void attn_kernel(
    const u32* __restrict__ Qh, const u32* __restrict__ Ql,
    const u32* __restrict__ Kh, const u32* __restrict__ Kl,
    const u32* __restrict__ Vh, const u32* __restrict__ Vl,
    u16* __restrict__ Ch, u16* __restrict__ Cl)
{
    extern __shared__ u32 sm[];
    const u32 smb = (u32)__cvta_generic_to_shared(sm);

    const int tid = threadIdx.x, lane = tid&31, wid = tid>>5;
    const int g = lane>>2, t4 = lane&3;
    const int h = blockIdx.y, q0 = blockIdx.x*128;
    const int row = wid*16;

#pragma unroll
    for (int j=0;j<8;j++){
        int i = tid + j*256;
        int plane = i>>10, rem = i&1023;
        int r = rem>>3, c = rem&7;
        const u32* src = (plane ? Ql : Qh) + ((size_t)(h*SQ + q0 + r))*32 + c*4;
        cp16(smb + ((plane ? 128*AS : 0) + r*AS + c*4)*4, src);
    }
    cp_commit();

    auto issueKV = [&](int t, int st){
        u32 base = 2*128*AS + st*4*KVW;
#pragma unroll
        for (int j=0;j<2;j++){
            int i = tid + j*256;
            int r = i>>3, c = i&7;
            cp16(smb + (base +           r*AS + c*4)*4, Kh + ((size_t)(h*SQ + t*64 + r))*32 + c*4);
            cp16(smb + (base +   KVW +   r*AS + c*4)*4, Kl + ((size_t)(h*SQ + t*64 + r))*32 + c*4);
            cp16(smb + (base + 2*KVW +   r*AS + c*4)*4, Vh + ((size_t)(h*DKH + r))*1024 + t*32 + c*4);
            cp16(smb + (base + 3*KVW +   r*AS + c*4)*4, Vl + ((size_t)(h*DKH + r))*1024 + t*32 + c*4);
        }
        cp_commit();
    };
    issueKV(0,0);

    float oacc[8][4];
#pragma unroll
    for (int j=0;j<8;j++)
#pragma unroll
        for (int e=0;e<4;e++) oacc[j][e]=0.f;
    float m0r=-1e30f, m1r=-1e30f, l0r=0.f, l1r=0.f;

    for (int t=0; t<SQ/64; t++){
        const int st = t & 1;
        if (t+1 < SQ/64) { issueKV(t+1, st^1); cp_wait<1>(); }
        else cp_wait<0>();
        __syncthreads();

        u32 kbase = 2*128*AS + st*4*KVW;
        u32 vbase = kbase + 2*KVW;

        float sc[8][4];
#pragma unroll
        for (int j=0;j<8;j++)
#pragma unroll
            for (int e=0;e<4;e++) sc[j][e]=0.f;
#pragma unroll
        for (int ks=0;ks<4;ks++){
            u32 qh[4], ql[4];
            int rowb = row + (lane&15);
            u32 wq = rowb*AS + ks*8 + (lane>>4)*4;
            ldsm4(qh[0],qh[1],qh[2],qh[3], smb + wq*4);
            ldsm4(ql[0],ql[1],ql[2],ql[3], smb + (wq + 128*AS)*4);
#pragma unroll
            for (int p=0;p<4;p++){
                int nb = p*16 + ((lane>>4)<<3) + (lane&7);
                u32 w = kbase + nb*AS + ks*8 + ((lane>>3)&1)*4;
                u32 bh[4], bl[4];
                ldsm4(bh[0],bh[1],bh[2],bh[3], smb + w*4);
                ldsm4(bl[0],bl[1],bl[2],bl[3], smb + (w+KVW)*4);
                mma3(sc[2*p  ], qh, ql, bh+0, bl+0);
                mma3(sc[2*p+1], qh, ql, bh+2, bl+2);
            }
        }

        float tm0=-1e30f, tm1=-1e30f;
#pragma unroll
        for (int j=0;j<8;j++){
            tm0 = fmaxf(tm0, fmaxf(sc[j][0], sc[j][1]));
            tm1 = fmaxf(tm1, fmaxf(sc[j][2], sc[j][3]));
        }
        tm0 = fmaxf(tm0, __shfl_xor_sync(0xffffffffu, tm0, 1));
        tm0 = fmaxf(tm0, __shfl_xor_sync(0xffffffffu, tm0, 2));
        tm1 = fmaxf(tm1, __shfl_xor_sync(0xffffffffu, tm1, 1));
        tm1 = fmaxf(tm1, __shfl_xor_sync(0xffffffffu, tm1, 2));
        float mn0 = fmaxf(m0r, tm0), mn1 = fmaxf(m1r, tm1);
        float c0 = __expf(m0r - mn0), c1 = __expf(m1r - mn1);
        float rs0=0.f, rs1=0.f;
#pragma unroll
        for (int j=0;j<8;j++){
            sc[j][0]=__expf(sc[j][0]-mn0); sc[j][1]=__expf(sc[j][1]-mn0);
            sc[j][2]=__expf(sc[j][2]-mn1); sc[j][3]=__expf(sc[j][3]-mn1);
            rs0 += sc[j][0]+sc[j][1]; rs1 += sc[j][2]+sc[j][3];
        }
        rs0 += __shfl_xor_sync(0xffffffffu, rs0, 1);
        rs0 += __shfl_xor_sync(0xffffffffu, rs0, 2);
        rs1 += __shfl_xor_sync(0xffffffffu, rs1, 1);
        rs1 += __shfl_xor_sync(0xffffffffu, rs1, 2);
        l0r = l0r*c0 + rs0; l1r = l1r*c1 + rs1;
        m0r = mn0; m1r = mn1;
#pragma unroll
        for (int j=0;j<8;j++){
            oacc[j][0]*=c0; oacc[j][1]*=c0; oacc[j][2]*=c1; oacc[j][3]*=c1;
        }

#pragma unroll
        for (int s=0;s<4;s++){
            u32 ph[4], pl[4];
            split_pack(sc[2*s  ][0], sc[2*s  ][1], ph[0], pl[0]);
            split_pack(sc[2*s  ][2], sc[2*s  ][3], ph[1], pl[1]);
            split_pack(sc[2*s+1][0], sc[2*s+1][1], ph[2], pl[2]);
            split_pack(sc[2*s+1][2], sc[2*s+1][3], ph[3], pl[3]);
#pragma unroll
            for (int p=0;p<4;p++){
                int nb = p*16 + ((lane>>4)<<3) + (lane&7);
                u32 w = vbase + nb*AS + s*8 + ((lane>>3)&1)*4;
                u32 bh[4], bl[4];
                ldsm4(bh[0],bh[1],bh[2],bh[3], smb + w*4);
                ldsm4(bl[0],bl[1],bl[2],bl[3], smb + (w+KVW)*4);
                mma3(oacc[2*p  ], ph, pl, bh+0, bl+0);
                mma3(oacc[2*p+1], ph, pl, bh+2, bl+2);
            }
        }
        __syncthreads();
    }

    float inv0 = 1.f/l0r, inv1 = 1.f/l1r;
    int r0 = q0 + row + g, r1 = r0+8;
#pragma unroll
    for (int j=0;j<8;j++){
        int col = h*DKH + j*8 + t4*2;
        u32 hh, ll;
        split_pack(oacc[j][0]*inv0, oacc[j][1]*inv0, hh, ll);
        ((u32*)Ch)[(r0*NHID + col)>>1] = hh;
        ((u32*)Cl)[(r0*NHID + col)>>1] = ll;
        split_pack(oacc[j][2]*inv1, oacc[j][3]*inv1, hh, ll);
        ((u32*)Ch)[(r1*NHID + col)>>1] = hh;
        ((u32*)Cl)[(r1*NHID + col)>>1] = ll;
    }
}

// ---------------------------------------------------------------------------
extern "C" void kernel_launch(void* const* d_in, const int* in_sizes, int n_in,
                              void* d_out, int out_size)
{
    const float* Q  = (const float*)d_in[0];
    const float* K  = (const float*)d_in[1];
    const float* V  = (const float*)d_in[2];
    const float* Wq = (const float*)d_in[3];
    const float* bq = (const float*)d_in[4];
    const float* Wk = (const float*)d_in[5];
    const float* bk = (const float*)d_in[6];
    const float* Wv = (const float*)d_in[7];
    const float* bv = (const float*)d_in[8];
    const float* Wo = (const float*)d_in[9];
    const float* bo = (const float*)d_in[10];
    float* out = (float*)d_out;

    u16 *xh,*xl,*wth,*wtl,*woth,*wotl;
    u16 *qh,*ql,*kh,*kl,*vth,*vtl,*ch,*cl;
    cudaGetSymbolAddress((void**)&xh,   g_xh);
    cudaGetSymbolAddress((void**)&xl,   g_xl);
    cudaGetSymbolAddress((void**)&wth,  g_wth);
    cudaGetSymbolAddress((void**)&wtl,  g_wtl);
    cudaGetSymbolAddress((void**)&woth, g_woth);
    cudaGetSymbolAddress((void**)&wotl, g_wotl);
    cudaGetSymbolAddress((void**)&qh,   g_qh);
    cudaGetSymbolAddress((void**)&ql,   g_ql);
    cudaGetSymbolAddress((void**)&kh,   g_kh);
    cudaGetSymbolAddress((void**)&kl,   g_kl);
    cudaGetSymbolAddress((void**)&vth,  g_vth);
    cudaGetSymbolAddress((void**)&vtl,  g_vtl);
    cudaGetSymbolAddress((void**)&ch,   g_ch);
    cudaGetSymbolAddress((void**)&cl,   g_cl);

    cudaFuncSetAttribute(proj5_kernel,
                         cudaFuncAttributeMaxDynamicSharedMemorySize, GEMM5_SMEM);
    cudaFuncSetAttribute(out5_kernel,
                         cudaFuncAttributeMaxDynamicSharedMemorySize, GEMM5_SMEM);
    cudaFuncSetAttribute(attn_kernel,
                         cudaFuncAttributeMaxDynamicSharedMemorySize, ATTN_SMEM);

    // fused pre-pass: one launch
    prepass_kernel<<<7168, 256>>>(Q, K, V, Wq, Wk, Wv, Wo,
                                  xh, xl, wth, wtl, woth, wotl);

    dim3 pg(NH/2, SQ/128, 3);     // (8, 16, 3)
    proj5_kernel<<<pg, 256, GEMM5_SMEM>>>((u32*)xh,(u32*)xl,(u32*)wth,(u32*)wtl,
                                          bq, bk, bv,
                                          qh, ql, kh, kl, vth, vtl);

    dim3 ag(SQ/128, NH);          // (16, 16)
    attn_kernel<<<ag, 256, ATTN_SMEM>>>((u32*)qh,(u32*)ql,(u32*)kh,(u32*)kl,
                                        (u32*)vth,(u32*)vtl, ch, cl);

    dim3 og(DM/128, SQ/128);      // (8, 16)
    out5_kernel<<<og, 256, GEMM5_SMEM>>>((u32*)ch,(u32*)cl,(u32*)woth,(u32*)wotl,
                                         bo, out);
}